// round 4
// baseline (speedup 1.0000x reference)
#include <cuda_runtime.h>
#include <math.h>

#define BDIM 1024
#define SEQ  2048
#define NH   16
#define DKH  64
#define HIDN 4096
#define MROWS 4096   // B*S
#define NB   2

// ---------------- scratch (static device globals; no allocation) ----------------
__device__ float g_Q  [MROWS * BDIM];
__device__ float g_K  [MROWS * BDIM];
__device__ float g_V  [MROWS * BDIM];
__device__ float g_att[MROWS * BDIM];
__device__ float g_s1 [MROWS * BDIM];
__device__ float g_x1 [MROWS * BDIM];
__device__ float g_hid[MROWS * HIDN];
__device__ float g_s2 [MROWS * BDIM];

enum { MODE_PLAIN = 0, MODE_RELU = 1, MODE_RES = 2, MODE_SPLIT = 3 };

// ---------------- SGEMM: C[M,N] = A[M,K] @ B[K,N] + bias (+epilogue) ----------------
// 128x128 tile, BK=8, 256 threads, 8x8 per thread (two 4-wide halves).
__global__ __launch_bounds__(256, 2) void sgemm_kernel(
    const float* __restrict__ A, const float* __restrict__ B,
    const float* __restrict__ bias, const float* __restrict__ R,
    float* __restrict__ C, int M, int N, int K, int mode)
{
    __shared__ float As[8][128];
    __shared__ float Bs[8][128];

    const int tid  = threadIdx.x;
    const int tx   = tid & 15;
    const int ty   = tid >> 4;
    const int row0 = blockIdx.y * 128;
    const int col0 = blockIdx.x * 128;

    const int aRow = tid >> 1;
    const int aCol = (tid & 1) * 4;
    const int bRow = tid >> 5;
    const int bCol = (tid & 31) * 4;

    const float* Ag = A + (size_t)(row0 + aRow) * K + aCol;
    const float* Bg = B + (size_t)bRow * N + col0 + bCol;

    float acc[8][8];
#pragma unroll
    for (int i = 0; i < 8; i++)
#pragma unroll
        for (int j = 0; j < 8; j++) acc[i][j] = 0.f;

    for (int k0 = 0; k0 < K; k0 += 8) {
        float4 av = *(const float4*)(Ag + k0);
        As[aCol + 0][aRow] = av.x;
        As[aCol + 1][aRow] = av.y;
        As[aCol + 2][aRow] = av.z;
        As[aCol + 3][aRow] = av.w;
        *(float4*)&Bs[bRow][bCol] = *(const float4*)(Bg + (size_t)k0 * N);
        __syncthreads();

#pragma unroll
        for (int k = 0; k < 8; k++) {
            float4 a0 = *(const float4*)&As[k][ty * 4];
            float4 a1 = *(const float4*)&As[k][64 + ty * 4];
            float4 b0 = *(const float4*)&Bs[k][tx * 4];
            float4 b1 = *(const float4*)&Bs[k][64 + tx * 4];
            float ra[8] = {a0.x, a0.y, a0.z, a0.w, a1.x, a1.y, a1.z, a1.w};
            float rb[8] = {b0.x, b0.y, b0.z, b0.w, b1.x, b1.y, b1.z, b1.w};
#pragma unroll
            for (int i = 0; i < 8; i++)
#pragma unroll
                for (int j = 0; j < 8; j++)
                    acc[i][j] = fmaf(ra[i], rb[j], acc[i][j]);
        }
        __syncthreads();
    }

    // epilogue
#pragma unroll
    for (int i = 0; i < 8; i++) {
        int m = row0 + ((i < 4) ? (ty * 4 + i) : (64 + ty * 4 + i - 4));
#pragma unroll
        for (int jh = 0; jh < 2; jh++) {
            int n = col0 + ((jh == 0) ? (tx * 4) : (64 + tx * 4));
            float4 v;
            v.x = acc[i][jh * 4 + 0];
            v.y = acc[i][jh * 4 + 1];
            v.z = acc[i][jh * 4 + 2];
            v.w = acc[i][jh * 4 + 3];
            float4 bz = *(const float4*)&bias[n];
            v.x += bz.x; v.y += bz.y; v.z += bz.z; v.w += bz.w;
            if (mode == MODE_RELU) {
                v.x = fmaxf(v.x, 0.f); v.y = fmaxf(v.y, 0.f);
                v.z = fmaxf(v.z, 0.f); v.w = fmaxf(v.w, 0.f);
            } else if (mode == MODE_RES) {
                float4 r4 = *(const float4*)&R[(size_t)m * N + n];
                v.x += r4.x; v.y += r4.y; v.z += r4.z; v.w += r4.w;
            }
            if (mode == MODE_SPLIT) {
                int hh = n >> 6, dk = n & 63;
                int bb = m >> 11, s = m & 2047;
                *(float4*)&C[(((size_t)(bb * NH + hh)) * SEQ + s) * DKH + dk] = v;
            } else {
                *(float4*)&C[(size_t)m * N + n] = v;
            }
        }
    }
}

// ---------------- Fused flash attention (fp32) ----------------
// Q,K,V: [B,H,S,DK]. Output written back in [B,S,D] layout.
// CTA: 64 queries x DK=64; 256 threads as 16x16, 4x4 per thread.
#define AST 65

__global__ __launch_bounds__(256) void attn_kernel(
    const float* __restrict__ Q, const float* __restrict__ Kg,
    const float* __restrict__ Vg, const int* __restrict__ mask,
    float* __restrict__ O)
{
    extern __shared__ float sm[];
    float* Qs = sm;
    float* Ks = Qs + 64 * AST;
    float* Vs = Ks + 64 * AST;
    float* Ps = Vs + 64 * AST;
    int*   msk = (int*)(Ps + 64 * AST);

    const int tid = threadIdx.x;
    const int tx  = tid & 15;
    const int ty  = tid >> 4;
    const int q0  = blockIdx.x * 64;
    const int h   = blockIdx.y;
    const int bz  = blockIdx.z;

    const size_t headoff = ((size_t)(bz * NH + h)) * SEQ * DKH;
    const float* Qb = Q  + headoff;
    const float* Kb = Kg + headoff;
    const float* Vb = Vg + headoff;

    {   // load Q tile
        int r  = tid >> 2;
        int d0 = (tid & 3) * 16;
        const float* src = Qb + (size_t)(q0 + r) * DKH + d0;
#pragma unroll
        for (int u = 0; u < 4; u++) {
            float4 v4 = *(const float4*)(src + u * 4);
            float* dst = &Qs[r * AST + d0 + u * 4];
            dst[0] = v4.x; dst[1] = v4.y; dst[2] = v4.z; dst[3] = v4.w;
        }
    }

    float mrow[4], lrow[4], o[4][4];
#pragma unroll
    for (int i = 0; i < 4; i++) {
        mrow[i] = -INFINITY; lrow[i] = 0.f;
#pragma unroll
        for (int j = 0; j < 4; j++) o[i][j] = 0.f;
    }

    for (int kv0 = 0; kv0 < SEQ; kv0 += 64) {
        __syncthreads();
        {   // load K/V tiles + mask
            int r  = tid >> 2;
            int d0 = (tid & 3) * 16;
            const float* ks = Kb + (size_t)(kv0 + r) * DKH + d0;
            const float* vg = Vb + (size_t)(kv0 + r) * DKH + d0;
#pragma unroll
            for (int u = 0; u < 4; u++) {
                float4 k4 = *(const float4*)(ks + u * 4);
                float* kd = &Ks[r * AST + d0 + u * 4];
                kd[0] = k4.x; kd[1] = k4.y; kd[2] = k4.z; kd[3] = k4.w;
                float4 v4 = *(const float4*)(vg + u * 4);
                float* vd = &Vs[r * AST + d0 + u * 4];
                vd[0] = v4.x; vd[1] = v4.y; vd[2] = v4.z; vd[3] = v4.w;
            }
            if (tid < 64) msk[tid] = mask[bz * SEQ + kv0 + tid];
        }
        __syncthreads();

        // scores S = Q @ K^T
        float s[4][4];
#pragma unroll
        for (int i = 0; i < 4; i++)
#pragma unroll
            for (int j = 0; j < 4; j++) s[i][j] = 0.f;

        const float* qb0 = &Qs[(ty * 4) * AST];
        const float* kb0 = &Ks[(tx * 4) * AST];
#pragma unroll 8
        for (int k = 0; k < 64; k++) {
            float qv[4], kv[4];
            qv[0] = qb0[k];           qv[1] = qb0[AST + k];
            qv[2] = qb0[2 * AST + k]; qv[3] = qb0[3 * AST + k];
            kv[0] = kb0[k];           kv[1] = kb0[AST + k];
            kv[2] = kb0[2 * AST + k]; kv[3] = kb0[3 * AST + k];
#pragma unroll
            for (int i = 0; i < 4; i++)
#pragma unroll
                for (int j = 0; j < 4; j++)
                    s[i][j] = fmaf(qv[i], kv[j], s[i][j]);
        }

        // scale + mask
#pragma unroll
        for (int j = 0; j < 4; j++) {
            bool mz = (msk[tx * 4 + j] == 0);
#pragma unroll
            for (int i = 0; i < 4; i++)
                s[i][j] = mz ? -1e9f : s[i][j] * 0.125f;
        }

        // online softmax
#pragma unroll
        for (int i = 0; i < 4; i++) {
            float rm = fmaxf(fmaxf(s[i][0], s[i][1]), fmaxf(s[i][2], s[i][3]));
#pragma unroll
            for (int off = 8; off > 0; off >>= 1)
                rm = fmaxf(rm, __shfl_xor_sync(0xffffffffu, rm, off));
            float mn    = fmaxf(mrow[i], rm);
            float alpha = __expf(mrow[i] - mn);
            float rs    = 0.f;
#pragma unroll
            for (int j = 0; j < 4; j++) {
                float p = __expf(s[i][j] - mn);
                s[i][j] = p;
                rs += p;
            }
#pragma unroll
            for (int off = 8; off > 0; off >>= 1)
                rs += __shfl_xor_sync(0xffffffffu, rs, off);
            lrow[i] = lrow[i] * alpha + rs;
            mrow[i] = mn;
#pragma unroll
            for (int j = 0; j < 4; j++) o[i][j] *= alpha;
        }

        // stage P
#pragma unroll
        for (int i = 0; i < 4; i++)
#pragma unroll
            for (int j = 0; j < 4; j++)
                Ps[(ty * 4 + i) * AST + tx * 4 + j] = s[i][j];
        __syncwarp();

        // O += P @ V
        const float* pb0 = &Ps[(ty * 4) * AST];
        const float* vb0 = &Vs[tx * 4];
#pragma unroll 8
        for (int kk = 0; kk < 64; kk++) {
            float pv[4], vv[4];
            pv[0] = pb0[kk];           pv[1] = pb0[AST + kk];
            pv[2] = pb0[2 * AST + kk]; pv[3] = pb0[3 * AST + kk];
            vv[0] = vb0[kk * AST + 0]; vv[1] = vb0[kk * AST + 1];
            vv[2] = vb0[kk * AST + 2]; vv[3] = vb0[kk * AST + 3];
#pragma unroll
            for (int i = 0; i < 4; i++)
#pragma unroll
                for (int j = 0; j < 4; j++)
                    o[i][j] = fmaf(pv[i], vv[j], o[i][j]);
        }
    }

    // epilogue: normalize, write to [B,S,D]
#pragma unroll
    for (int i = 0; i < 4; i++) {
        float inv = 1.f / (lrow[i] > 0.f ? lrow[i] : 1.f);
        int m = q0 + ty * 4 + i;
        float4 v4;
        v4.x = o[i][0] * inv; v4.y = o[i][1] * inv;
        v4.z = o[i][2] * inv; v4.w = o[i][3] * inv;
        *(float4*)&O[((size_t)bz * SEQ + m) * BDIM + h * DKH + tx * 4] = v4;
    }
}

// ---------------- LayerNorm: one CTA per row of 1024 ----------------
__global__ __launch_bounds__(256) void ln_kernel(
    const float* __restrict__ X, const float* __restrict__ g,
    const float* __restrict__ b, float* __restrict__ Y)
{
    __shared__ float red[2][8];
    __shared__ float stats[2];
    const int row = blockIdx.x;
    const int tid = threadIdx.x;

    const float4 v = ((const float4*)(X + (size_t)row * BDIM))[tid];
    float s = v.x + v.y + v.z + v.w;
    float q = v.x * v.x + v.y * v.y + v.z * v.z + v.w * v.w;
#pragma unroll
    for (int o = 16; o > 0; o >>= 1) {
        s += __shfl_xor_sync(0xffffffffu, s, o);
        q += __shfl_xor_sync(0xffffffffu, q, o);
    }
    const int lane = tid & 31, w = tid >> 5;
    if (lane == 0) { red[0][w] = s; red[1][w] = q; }
    __syncthreads();
    if (tid < 32) {
        s = (tid < 8) ? red[0][tid] : 0.f;
        q = (tid < 8) ? red[1][tid] : 0.f;
#pragma unroll
        for (int o = 4; o > 0; o >>= 1) {
            s += __shfl_xor_sync(0xffffffffu, s, o);
            q += __shfl_xor_sync(0xffffffffu, q, o);
        }
        if (tid == 0) {
            float mean = s * (1.f / BDIM);
            stats[0] = mean;
            stats[1] = rsqrtf(q * (1.f / BDIM) - mean * mean + 1e-5f);
        }
    }
    __syncthreads();
    const float mean = stats[0], rinv = stats[1];
    const float4 gg = ((const float4*)g)[tid];
    const float4 bb = ((const float4*)b)[tid];
    float4 o4;
    o4.x = (v.x - mean) * rinv * gg.x + bb.x;
    o4.y = (v.y - mean) * rinv * gg.y + bb.y;
    o4.z = (v.z - mean) * rinv * gg.z + bb.z;
    o4.w = (v.w - mean) * rinv * gg.w + bb.w;
    ((float4*)(Y + (size_t)row * BDIM))[tid] = o4;
}

// ---------------- launcher ----------------
extern "C" void kernel_launch(void* const* d_in, const int* in_sizes, int n_in,
                              void* d_out, int out_size)
{
    const float* x    = (const float*)d_in[0];
    const float* y    = (const float*)d_in[1];
    const int*   mask = (const int*)  d_in[2];
    const float* Wq = (const float*)d_in[3];  const float* bq = (const float*)d_in[4];
    const float* Wk = (const float*)d_in[5];  const float* bk = (const float*)d_in[6];
    const float* Wv = (const float*)d_in[7];  const float* bv = (const float*)d_in[8];
    const float* Wo = (const float*)d_in[9];  const float* bo = (const float*)d_in[10];
    const float* W1 = (const float*)d_in[11]; const float* b1 = (const float*)d_in[12];
    const float* W2 = (const float*)d_in[13]; const float* b2 = (const float*)d_in[14];
    const float* g1 = (const float*)d_in[15]; const float* be1 = (const float*)d_in[16];
    const float* g2 = (const float*)d_in[17]; const float* be2 = (const float*)d_in[18];
    float* out = (float*)d_out;

    float *Qp, *Kp, *Vp, *attp, *s1p, *x1p, *hp, *s2p;
    cudaGetSymbolAddress((void**)&Qp,   g_Q);
    cudaGetSymbolAddress((void**)&Kp,   g_K);
    cudaGetSymbolAddress((void**)&Vp,   g_V);
    cudaGetSymbolAddress((void**)&attp, g_att);
    cudaGetSymbolAddress((void**)&s1p,  g_s1);
    cudaGetSymbolAddress((void**)&x1p,  g_x1);
    cudaGetSymbolAddress((void**)&hp,   g_hid);
    cudaGetSymbolAddress((void**)&s2p,  g_s2);

    dim3 blk(256);
    dim3 gD(BDIM / 128, MROWS / 128);   // (8, 32)
    dim3 gH(HIDN / 128, MROWS / 128);   // (32, 32)

    // QKV projections -> [B,H,S,DK]
    sgemm_kernel<<<gD, blk>>>(x, Wq, bq, nullptr, Qp, MROWS, BDIM, BDIM, MODE_SPLIT);
    sgemm_kernel<<<gD, blk>>>(y, Wk, bk, nullptr, Kp, MROWS, BDIM, BDIM, MODE_SPLIT);
    sgemm_kernel<<<gD, blk>>>(y, Wv, bv, nullptr, Vp, MROWS, BDIM, BDIM, MODE_SPLIT);

    // fused attention -> [B,S,D]
    size_t shm = (size_t)(4 * 64 * AST) * sizeof(float) + 64 * sizeof(int);
    cudaFuncSetAttribute(attn_kernel, cudaFuncAttributeMaxDynamicSharedMemorySize, (int)shm);
    attn_kernel<<<dim3(SEQ / 64, NH, NB), blk, shm>>>(Qp, Kp, Vp, mask, attp);

    // s1 = x + attn @ Wo + bo ; x1 = LN(s1)
    sgemm_kernel<<<gD, blk>>>(attp, Wo, bo, x, s1p, MROWS, BDIM, BDIM, MODE_RES);
    ln_kernel<<<MROWS, blk>>>(s1p, g1, be1, x1p);

    // FFN: h = relu(x1 @ W1 + b1); s2 = x1 + h @ W2 + b2; out = LN(s2)
    sgemm_kernel<<<gH, blk>>>(x1p, W1, b1, nullptr, hp, MROWS, HIDN, BDIM, MODE_RELU);
    sgemm_kernel<<<gD, blk>>>(hp, W2, b2, x1p, s2p, MROWS, BDIM, HIDN, MODE_RES);
    ln_kernel<<<MROWS, blk>>>(s2p, g2, be2, out);
}

// round 6
// speedup vs baseline: 1.4826x; 1.4826x over previous
#include <cuda_runtime.h>
#include <cuda_bf16.h>
#include <math.h>
#include <stdint.h>

#define BDIM 1024
#define SEQ  2048
#define NH   16
#define DKH  64
#define HIDN 4096
#define MROWS 4096   // B*S
#define NB   2

typedef __nv_bfloat16 bf16;

// ---------------- scratch (static device globals; no allocation) ----------------
__device__ float g_Q  [MROWS * BDIM];
__device__ float g_K  [MROWS * BDIM];
__device__ float g_V  [MROWS * BDIM];
__device__ float g_s1 [MROWS * BDIM];
__device__ float g_x1 [MROWS * BDIM];
__device__ float g_s2 [MROWS * BDIM];

__device__ bf16 g_xhi [MROWS * BDIM];
__device__ bf16 g_xlo [MROWS * BDIM];
__device__ bf16 g_yhi [MROWS * BDIM];
__device__ bf16 g_ylo [MROWS * BDIM];
__device__ bf16 g_ahi [MROWS * BDIM];   // attention output
__device__ bf16 g_alo [MROWS * BDIM];
__device__ bf16 g_x1hi[MROWS * BDIM];
__device__ bf16 g_x1lo[MROWS * BDIM];
__device__ bf16 g_hhi [MROWS * HIDN];
__device__ bf16 g_hlo [MROWS * HIDN];

// transposed + split weights: Wt[N][K]
__device__ bf16 g_wqT_hi[BDIM * BDIM], g_wqT_lo[BDIM * BDIM];
__device__ bf16 g_wkT_hi[BDIM * BDIM], g_wkT_lo[BDIM * BDIM];
__device__ bf16 g_wvT_hi[BDIM * BDIM], g_wvT_lo[BDIM * BDIM];
__device__ bf16 g_woT_hi[BDIM * BDIM], g_woT_lo[BDIM * BDIM];
__device__ bf16 g_w1T_hi[HIDN * BDIM], g_w1T_lo[HIDN * BDIM];
__device__ bf16 g_w2T_hi[BDIM * HIDN], g_w2T_lo[BDIM * HIDN];

enum { MODE_RELU_HL = 1, MODE_RES = 2, MODE_SPLIT = 3 };

// ======================= PTX helpers =======================
__device__ __forceinline__ uint32_t smem_u32(const void* p) {
    uint32_t a;
    asm("{ .reg .u64 t; cvta.to.shared.u64 t, %1; cvt.u32.u64 %0, t; }" : "=r"(a) : "l"(p));
    return a;
}
__device__ __forceinline__ void cp16(uint32_t s, const void* g) {
    asm volatile("cp.async.cg.shared.global [%0], [%1], 16;" :: "r"(s), "l"(g));
}
#define CP_COMMIT() asm volatile("cp.async.commit_group;" ::: "memory")
#define CP_WAIT0()  asm volatile("cp.async.wait_group 0;" ::: "memory")
#define CP_WAIT1()  asm volatile("cp.async.wait_group 1;" ::: "memory")

__device__ __forceinline__ void ldm_x4(uint32_t& r0, uint32_t& r1, uint32_t& r2, uint32_t& r3, uint32_t a) {
    asm volatile("ldmatrix.sync.aligned.m8n8.x4.shared.b16 {%0,%1,%2,%3}, [%4];"
                 : "=r"(r0), "=r"(r1), "=r"(r2), "=r"(r3) : "r"(a));
}
__device__ __forceinline__ void mma16816(float* c, const uint32_t* a, const uint32_t* b) {
    asm volatile("mma.sync.aligned.m16n8k16.row.col.f32.bf16.bf16.f32 "
                 "{%0,%1,%2,%3}, {%4,%5,%6,%7}, {%8,%9}, {%0,%1,%2,%3};"
                 : "+f"(c[0]), "+f"(c[1]), "+f"(c[2]), "+f"(c[3])
                 : "r"(a[0]), "r"(a[1]), "r"(a[2]), "r"(a[3]), "r"(b[0]), "r"(b[1]));
}

// ======================= mma.sync bf16 split-precision GEMM =======================
// C[M,N] = A[M,K] @ Wt[N,K]^T, hi/lo bf16 split, fp32 accum.
// CTA 128x128, BK=32, 256 threads = 8 warps (2 M x 4 N), warp tile 64x32.
#define BK 32
#define APAD 40                         // bf16 elems per smem row (32 + 8 pad)
#define TILE_B (128 * APAD * 2)         // 10240 bytes per tile
#define SLAB_B (4 * TILE_B)             // Ahi, Alo, Bhi, Blo
#define GEMM_SMEM (2 * SLAB_B)          // 81920 bytes

__global__ __launch_bounds__(256, 1) void mma_gemm(
    const bf16* __restrict__ Ahi, const bf16* __restrict__ Alo,
    const bf16* __restrict__ Bhi, const bf16* __restrict__ Blo,
    const float* __restrict__ bias, const float* __restrict__ R,
    float* __restrict__ outF, bf16* __restrict__ outHi, bf16* __restrict__ outLo,
    int M, int N, int K, int mode)
{
    extern __shared__ char sm[];
    const uint32_t smb = smem_u32(sm);
    const int tid = threadIdx.x;
    const int wid = tid >> 5;
    const int lid = tid & 31;
    const int warp_m = wid >> 2;        // 0..1
    const int warp_n = wid & 3;         // 0..3
    const int row0 = blockIdx.y * 128;
    const int col0 = blockIdx.x * 128;

    const bf16* src[4];
    src[0] = Ahi + (size_t)row0 * K;
    src[1] = Alo + (size_t)row0 * K;
    src[2] = Bhi + (size_t)col0 * K;
    src[3] = Blo + (size_t)col0 * K;

    const int NS = K / BK;

    // slab loader: 4 tiles x 128 rows x 32 bf16 (64B), padded rows
#define LOAD_SLAB(ST, KS) do {                                                \
        const uint32_t _sb = smb + (ST) * SLAB_B;                             \
        const int _ko = (KS) * BK;                                            \
        _Pragma("unroll")                                                     \
        for (int t = 0; t < 4; t++) {                                         \
            const bf16* g = src[t] + _ko;                                     \
            const uint32_t tb = _sb + t * TILE_B;                             \
            _Pragma("unroll")                                                 \
            for (int u = 0; u < 2; u++) {                                     \
                int p = tid + u * 256;                                        \
                int r = p >> 2, c = p & 3;                                    \
                cp16(tb + (uint32_t)(r * (APAD * 2) + c * 16),                \
                     g + (size_t)r * K + c * 8);                              \
            }                                                                 \
        }                                                                     \
        CP_COMMIT();                                                          \
    } while (0)

    float acc[4][4][4];
#pragma unroll
    for (int i = 0; i < 4; i++)
#pragma unroll
        for (int j = 0; j < 4; j++)
#pragma unroll
            for (int f = 0; f < 4; f++) acc[i][j][f] = 0.f;

    LOAD_SLAB(0, 0);

    // per-thread ldmatrix addressing (same formula for A and B pairs)
    const uint32_t lrow = (uint32_t)(lid & 15);
    const uint32_t lcol16 = (uint32_t)(lid >> 4) * 16;

    for (int s = 0; s < NS; s++) {
        const int st = s & 1;
        if (s + 1 < NS) { LOAD_SLAB(st ^ 1, s + 1); CP_WAIT1(); }
        else            { CP_WAIT0(); }
        __syncthreads();

        const uint32_t sb  = smb + st * SLAB_B;
        const uint32_t ab_hi = sb;
        const uint32_t ab_lo = sb + TILE_B;
        const uint32_t bb_hi = sb + 2 * TILE_B;
        const uint32_t bb_lo = sb + 3 * TILE_B;

#pragma unroll
        for (int kk = 0; kk < 2; kk++) {
            const uint32_t koff = kk * 32 + lcol16;  // 16 bf16 = 32B per kstep

            uint32_t ah[4][4], al[4][4];
#pragma unroll
            for (int mi = 0; mi < 4; mi++) {
                uint32_t ra = (uint32_t)((warp_m * 64 + mi * 16 + lrow) * (APAD * 2)) + koff;
                ldm_x4(ah[mi][0], ah[mi][1], ah[mi][2], ah[mi][3], ab_hi + ra);
                ldm_x4(al[mi][0], al[mi][1], al[mi][2], al[mi][3], ab_lo + ra);
            }
            uint32_t bh[4][2], bl[4][2];
#pragma unroll
            for (int nt = 0; nt < 2; nt++) {
                uint32_t rb = (uint32_t)((warp_n * 32 + nt * 16 + lrow) * (APAD * 2)) + koff;
                uint32_t r0, r1, r2, r3;
                ldm_x4(r0, r1, r2, r3, bb_hi + rb);
                bh[nt * 2 + 0][0] = r0; bh[nt * 2 + 0][1] = r2;
                bh[nt * 2 + 1][0] = r1; bh[nt * 2 + 1][1] = r3;
                ldm_x4(r0, r1, r2, r3, bb_lo + rb);
                bl[nt * 2 + 0][0] = r0; bl[nt * 2 + 0][1] = r2;
                bl[nt * 2 + 1][0] = r1; bl[nt * 2 + 1][1] = r3;
            }
#pragma unroll
            for (int mi = 0; mi < 4; mi++)
#pragma unroll
                for (int ni = 0; ni < 4; ni++) {
                    mma16816(acc[mi][ni], ah[mi], bh[ni]);
                    mma16816(acc[mi][ni], ah[mi], bl[ni]);
                    mma16816(acc[mi][ni], al[mi], bh[ni]);
                }
        }
        __syncthreads();
    }

    // ---- epilogue: direct global writes (float2 per fragment half) ----
    const int qr = lid >> 2;            // 0..7
    const int qc = (lid & 3) * 2;       // 0,2,4,6
#pragma unroll
    for (int mi = 0; mi < 4; mi++) {
#pragma unroll
        for (int ni = 0; ni < 4; ni++) {
            const int n = col0 + warp_n * 32 + ni * 8 + qc;
            const float b0 = bias[n], b1 = bias[n + 1];
#pragma unroll
            for (int half = 0; half < 2; half++) {
                const int m = row0 + warp_m * 64 + mi * 16 + qr + half * 8;
                float v0 = acc[mi][ni][half * 2 + 0] + b0;
                float v1 = acc[mi][ni][half * 2 + 1] + b1;
                if (mode == MODE_RES) {
                    const float* rp = &R[(size_t)m * N + n];
                    v0 += rp[0]; v1 += rp[1];
                    float2 o2 = {v0, v1};
                    *(float2*)&outF[(size_t)m * N + n] = o2;
                } else if (mode == MODE_SPLIT) {
                    int hh = n >> 6, dk = n & 63, bb = m >> 11, ss = m & 2047;
                    float2 o2 = {v0, v1};
                    *(float2*)&outF[(((size_t)(bb * NH + hh)) * SEQ + ss) * DKH + dk] = o2;
                } else { // MODE_RELU_HL
                    v0 = fmaxf(v0, 0.f); v1 = fmaxf(v1, 0.f);
                    bf16 h0 = __float2bfloat16(v0), h1 = __float2bfloat16(v1);
                    __nv_bfloat162 p;
                    p.x = h0; p.y = h1;
                    *(__nv_bfloat162*)&outHi[(size_t)m * N + n] = p;
                    p.x = __float2bfloat16(v0 - __bfloat162float(h0));
                    p.y = __float2bfloat16(v1 - __bfloat162float(h1));
                    *(__nv_bfloat162*)&outLo[(size_t)m * N + n] = p;
                }
            }
        }
    }
}

// ======================= weight transpose + hi/lo split =======================
__global__ __launch_bounds__(256) void wtrans_kernel(
    const float* __restrict__ W, bf16* __restrict__ hiT, bf16* __restrict__ loT,
    int K, int N)
{
    __shared__ float t[32][33];
    const int n0 = blockIdx.x * 32, k0 = blockIdx.y * 32;
    const int tx = threadIdx.x, ty = threadIdx.y;
#pragma unroll
    for (int j = 0; j < 4; j++)
        t[ty + j * 8][tx] = W[(size_t)(k0 + ty + j * 8) * N + n0 + tx];
    __syncthreads();
#pragma unroll
    for (int j = 0; j < 4; j++) {
        float v = t[tx][ty + j * 8];
        bf16 h = __float2bfloat16(v);
        size_t o = (size_t)(n0 + ty + j * 8) * K + k0 + tx;
        hiT[o] = h;
        loT[o] = __float2bfloat16(v - __bfloat162float(h));
    }
}

// ======================= fp32 -> hi/lo split =======================
__global__ __launch_bounds__(256) void cvt_hilo(
    const float* __restrict__ X, bf16* __restrict__ hi, bf16* __restrict__ lo)
{
    const int i = (blockIdx.x * 256 + threadIdx.x) * 4;
    const float4 v = *(const float4*)(X + i);
    bf16 h0 = __float2bfloat16(v.x), h1 = __float2bfloat16(v.y);
    bf16 h2 = __float2bfloat16(v.z), h3 = __float2bfloat16(v.w);
    __nv_bfloat162 a, b;
    a.x = h0; a.y = h1; b.x = h2; b.y = h3;
    *(__nv_bfloat162*)(hi + i)     = a;
    *(__nv_bfloat162*)(hi + i + 2) = b;
    a.x = __float2bfloat16(v.x - __bfloat162float(h0));
    a.y = __float2bfloat16(v.y - __bfloat162float(h1));
    b.x = __float2bfloat16(v.z - __bfloat162float(h2));
    b.y = __float2bfloat16(v.w - __bfloat162float(h3));
    *(__nv_bfloat162*)(lo + i)     = a;
    *(__nv_bfloat162*)(lo + i + 2) = b;
}

// ======================= Fused flash attention (fp32) =======================
#define AST 65
__global__ __launch_bounds__(256) void attn_kernel(
    const float* __restrict__ Q, const float* __restrict__ Kg,
    const float* __restrict__ Vg, const int* __restrict__ mask,
    bf16* __restrict__ Ohi, bf16* __restrict__ Olo)
{
    extern __shared__ float smf[];
    float* Qs = smf;
    float* Ks = Qs + 64 * AST;
    float* Vs = Ks + 64 * AST;
    float* Ps = Vs + 64 * AST;
    int*   msk = (int*)(Ps + 64 * AST);

    const int tid = threadIdx.x;
    const int tx  = tid & 15;
    const int ty  = tid >> 4;
    const int q0  = blockIdx.x * 64;
    const int h   = blockIdx.y;
    const int bz  = blockIdx.z;

    const size_t headoff = ((size_t)(bz * NH + h)) * SEQ * DKH;
    const float* Qb = Q  + headoff;
    const float* Kb = Kg + headoff;
    const float* Vb = Vg + headoff;

    {
        int r = tid >> 2, d0 = (tid & 3) * 16;
        const float* s = Qb + (size_t)(q0 + r) * DKH + d0;
#pragma unroll
        for (int u = 0; u < 4; u++) {
            float4 v4 = *(const float4*)(s + u * 4);
            float* dst = &Qs[r * AST + d0 + u * 4];
            dst[0] = v4.x; dst[1] = v4.y; dst[2] = v4.z; dst[3] = v4.w;
        }
    }

    float mrow[4], lrow[4], o[4][4];
#pragma unroll
    for (int i = 0; i < 4; i++) {
        mrow[i] = -INFINITY; lrow[i] = 0.f;
#pragma unroll
        for (int j = 0; j < 4; j++) o[i][j] = 0.f;
    }

    for (int kv0 = 0; kv0 < SEQ; kv0 += 64) {
        __syncthreads();
        {
            int r = tid >> 2, d0 = (tid & 3) * 16;
            const float* ks = Kb + (size_t)(kv0 + r) * DKH + d0;
            const float* vg = Vb + (size_t)(kv0 + r) * DKH + d0;
#pragma unroll
            for (int u = 0; u < 4; u++) {
                float4 k4 = *(const float4*)(ks + u * 4);
                float* kd = &Ks[r * AST + d0 + u * 4];
                kd[0] = k4.x; kd[1] = k4.y; kd[2] = k4.z; kd[3] = k4.w;
                float4 v4 = *(const float4*)(vg + u * 4);
                float* vd = &Vs[r * AST + d0 + u * 4];
                vd[0] = v4.x; vd[1] = v4.y; vd[2] = v4.z; vd[3] = v4.w;
            }
            if (tid < 64) msk[tid] = mask[bz * SEQ + kv0 + tid];
        }
        __syncthreads();

        float s[4][4];
#pragma unroll
        for (int i = 0; i < 4; i++)
#pragma unroll
            for (int j = 0; j < 4; j++) s[i][j] = 0.f;

        const float* qb0 = &Qs[(ty * 4) * AST];
        const float* kb0 = &Ks[(tx * 4) * AST];
#pragma unroll 8
        for (int k = 0; k < 64; k++) {
            float qv[4], kv[4];
            qv[0] = qb0[k];           qv[1] = qb0[AST + k];
            qv[2] = qb0[2 * AST + k]; qv[3] = qb0[3 * AST + k];
            kv[0] = kb0[k];           kv[1] = kb0[AST + k];
            kv[2] = kb0[2 * AST + k]; kv[3] = kb0[3 * AST + k];
#pragma unroll
            for (int i = 0; i < 4; i++)
#pragma unroll
                for (int j = 0; j < 4; j++)
                    s[i][j] = fmaf(qv[i], kv[j], s[i][j]);
        }

#pragma unroll
        for (int j = 0; j < 4; j++) {
            bool mz = (msk[tx * 4 + j] == 0);
#pragma unroll
            for (int i = 0; i < 4; i++)
                s[i][j] = mz ? -1e9f : s[i][j] * 0.125f;
        }

#pragma unroll
        for (int i = 0; i < 4; i++) {
            float rm = fmaxf(fmaxf(s[i][0], s[i][1]), fmaxf(s[i][2], s[i][3]));
#pragma unroll
            for (int off = 8; off > 0; off >>= 1)
                rm = fmaxf(rm, __shfl_xor_sync(0xffffffffu, rm, off));
            float mn = fmaxf(mrow[i], rm);
            float alpha = __expf(mrow[i] - mn);
            float rs = 0.f;
#pragma unroll
            for (int j = 0; j < 4; j++) {
                float p = __expf(s[i][j] - mn);
                s[i][j] = p; rs += p;
            }
#pragma unroll
            for (int off = 8; off > 0; off >>= 1)
                rs += __shfl_xor_sync(0xffffffffu, rs, off);
            lrow[i] = lrow[i] * alpha + rs;
            mrow[i] = mn;
#pragma unroll
            for (int j = 0; j < 4; j++) o[i][j] *= alpha;
        }

#pragma unroll
        for (int i = 0; i < 4; i++)
#pragma unroll
            for (int j = 0; j < 4; j++)
                Ps[(ty * 4 + i) * AST + tx * 4 + j] = s[i][j];
        __syncwarp();

        const float* pb0 = &Ps[(ty * 4) * AST];
        const float* vb0 = &Vs[tx * 4];
#pragma unroll 8
        for (int kk = 0; kk < 64; kk++) {
            float pv[4], vv[4];
            pv[0] = pb0[kk];           pv[1] = pb0[AST + kk];
            pv[2] = pb0[2 * AST + kk]; pv[3] = pb0[3 * AST + kk];
            vv[0] = vb0[kk * AST + 0]; vv[1] = vb0[kk * AST + 1];
            vv[2] = vb0[kk * AST + 2]; vv[3] = vb0[kk * AST + 3];
#pragma unroll
            for (int i = 0; i < 4; i++)
#pragma unroll
                for (int j = 0; j < 4; j++)
                    o[i][j] = fmaf(pv[i], vv[j], o[i][j]);
        }
    }

    // epilogue: normalize, hi/lo split, write to [B,S,D]
#pragma unroll
    for (int i = 0; i < 4; i++) {
        float inv = 1.f / (lrow[i] > 0.f ? lrow[i] : 1.f);
        int m = q0 + ty * 4 + i;
        size_t base = ((size_t)bz * SEQ + m) * BDIM + h * DKH + tx * 4;
        float v0 = o[i][0] * inv, v1 = o[i][1] * inv;
        float v2 = o[i][2] * inv, v3 = o[i][3] * inv;
        bf16 h0 = __float2bfloat16(v0), h1 = __float2bfloat16(v1);
        bf16 h2 = __float2bfloat16(v2), h3 = __float2bfloat16(v3);
        __nv_bfloat162 p;
        p.x = h0; p.y = h1; *(__nv_bfloat162*)(Ohi + base)     = p;
        p.x = h2; p.y = h3; *(__nv_bfloat162*)(Ohi + base + 2) = p;
        p.x = __float2bfloat16(v0 - __bfloat162float(h0));
        p.y = __float2bfloat16(v1 - __bfloat162float(h1));
        *(__nv_bfloat162*)(Olo + base) = p;
        p.x = __float2bfloat16(v2 - __bfloat162float(h2));
        p.y = __float2bfloat16(v3 - __bfloat162float(h3));
        *(__nv_bfloat162*)(Olo + base + 2) = p;
    }
}

// ======================= LayerNorm (+ optional hi/lo output) =======================
__global__ __launch_bounds__(256) void ln_kernel(
    const float* __restrict__ X, const float* __restrict__ g,
    const float* __restrict__ b, float* __restrict__ Y,
    bf16* __restrict__ Yhi, bf16* __restrict__ Ylo)
{
    __shared__ float red[2][8];
    __shared__ float stats[2];
    const int row = blockIdx.x;
    const int tid = threadIdx.x;

    const float4 v = ((const float4*)(X + (size_t)row * BDIM))[tid];
    float s = v.x + v.y + v.z + v.w;
    float q = v.x * v.x + v.y * v.y + v.z * v.z + v.w * v.w;
#pragma unroll
    for (int o = 16; o > 0; o >>= 1) {
        s += __shfl_xor_sync(0xffffffffu, s, o);
        q += __shfl_xor_sync(0xffffffffu, q, o);
    }
    const int lane = tid & 31, w = tid >> 5;
    if (lane == 0) { red[0][w] = s; red[1][w] = q; }
    __syncthreads();
    if (tid < 32) {
        s = (tid < 8) ? red[0][tid] : 0.f;
        q = (tid < 8) ? red[1][tid] : 0.f;
#pragma unroll
        for (int o = 4; o > 0; o >>= 1) {
            s += __shfl_xor_sync(0xffffffffu, s, o);
            q += __shfl_xor_sync(0xffffffffu, q, o);
        }
        if (tid == 0) {
            float mean = s * (1.f / BDIM);
            stats[0] = mean;
            stats[1] = rsqrtf(q * (1.f / BDIM) - mean * mean + 1e-5f);
        }
    }
    __syncthreads();
    const float mean = stats[0], rinv = stats[1];
    const float4 gg = ((const float4*)g)[tid];
    const float4 bb = ((const float4*)b)[tid];
    float4 o4;
    o4.x = (v.x - mean) * rinv * gg.x + bb.x;
    o4.y = (v.y - mean) * rinv * gg.y + bb.y;
    o4.z = (v.z - mean) * rinv * gg.z + bb.z;
    o4.w = (v.w - mean) * rinv * gg.w + bb.w;
    if (Y) ((float4*)(Y + (size_t)row * BDIM))[tid] = o4;
    if (Yhi) {
        size_t base = (size_t)row * BDIM + tid * 4;
        bf16 h0 = __float2bfloat16(o4.x), h1 = __float2bfloat16(o4.y);
        bf16 h2 = __float2bfloat16(o4.z), h3 = __float2bfloat16(o4.w);
        __nv_bfloat162 p;
        p.x = h0; p.y = h1; *(__nv_bfloat162*)(Yhi + base)     = p;
        p.x = h2; p.y = h3; *(__nv_bfloat162*)(Yhi + base + 2) = p;
        p.x = __float2bfloat16(o4.x - __bfloat162float(h0));
        p.y = __float2bfloat16(o4.y - __bfloat162float(h1));
        *(__nv_bfloat162*)(Ylo + base) = p;
        p.x = __float2bfloat16(o4.z - __bfloat162float(h2));
        p.y = __float2bfloat16(o4.w - __bfloat162float(h3));
        *(__nv_bfloat162*)(Ylo + base + 2) = p;
    }
}

// ======================= launcher =======================
extern "C" void kernel_launch(void* const* d_in, const int* in_sizes, int n_in,
                              void* d_out, int out_size)
{
    const float* x    = (const float*)d_in[0];
    const float* y    = (const float*)d_in[1];
    const int*   mask = (const int*)  d_in[2];
    const float* Wq = (const float*)d_in[3];  const float* bq = (const float*)d_in[4];
    const float* Wk = (const float*)d_in[5];  const float* bk = (const float*)d_in[6];
    const float* Wv = (const float*)d_in[7];  const float* bv = (const float*)d_in[8];
    const float* Wo = (const float*)d_in[9];  const float* bo = (const float*)d_in[10];
    const float* W1 = (const float*)d_in[11]; const float* b1 = (const float*)d_in[12];
    const float* W2 = (const float*)d_in[13]; const float* b2 = (const float*)d_in[14];
    const float* g1 = (const float*)d_in[15]; const float* be1 = (const float*)d_in[16];
    const float* g2 = (const float*)d_in[17]; const float* be2 = (const float*)d_in[18];
    float* out = (float*)d_out;

    float *Qp, *Kp, *Vp, *s1p, *x1p, *s2p;
    bf16 *xhi, *xlo, *yhi, *ylo, *ahi, *alo, *x1hi, *x1lo, *hhi, *hlo;
    bf16 *wq_h, *wq_l, *wk_h, *wk_l, *wv_h, *wv_l, *wo_h, *wo_l, *w1_h, *w1_l, *w2_h, *w2_l;
    cudaGetSymbolAddress((void**)&Qp,  g_Q);   cudaGetSymbolAddress((void**)&Kp,  g_K);
    cudaGetSymbolAddress((void**)&Vp,  g_V);   cudaGetSymbolAddress((void**)&s1p, g_s1);
    cudaGetSymbolAddress((void**)&x1p, g_x1);  cudaGetSymbolAddress((void**)&s2p, g_s2);
    cudaGetSymbolAddress((void**)&xhi, g_xhi); cudaGetSymbolAddress((void**)&xlo, g_xlo);
    cudaGetSymbolAddress((void**)&yhi, g_yhi); cudaGetSymbolAddress((void**)&ylo, g_ylo);
    cudaGetSymbolAddress((void**)&ahi, g_ahi); cudaGetSymbolAddress((void**)&alo, g_alo);
    cudaGetSymbolAddress((void**)&x1hi, g_x1hi); cudaGetSymbolAddress((void**)&x1lo, g_x1lo);
    cudaGetSymbolAddress((void**)&hhi, g_hhi); cudaGetSymbolAddress((void**)&hlo, g_hlo);
    cudaGetSymbolAddress((void**)&wq_h, g_wqT_hi); cudaGetSymbolAddress((void**)&wq_l, g_wqT_lo);
    cudaGetSymbolAddress((void**)&wk_h, g_wkT_hi); cudaGetSymbolAddress((void**)&wk_l, g_wkT_lo);
    cudaGetSymbolAddress((void**)&wv_h, g_wvT_hi); cudaGetSymbolAddress((void**)&wv_l, g_wvT_lo);
    cudaGetSymbolAddress((void**)&wo_h, g_woT_hi); cudaGetSymbolAddress((void**)&wo_l, g_woT_lo);
    cudaGetSymbolAddress((void**)&w1_h, g_w1T_hi); cudaGetSymbolAddress((void**)&w1_l, g_w1T_lo);
    cudaGetSymbolAddress((void**)&w2_h, g_w2T_hi); cudaGetSymbolAddress((void**)&w2_l, g_w2T_lo);

    cudaFuncSetAttribute(mma_gemm, cudaFuncAttributeMaxDynamicSharedMemorySize, GEMM_SMEM);

    // ---- weight prep (transpose + hi/lo split) ----
    dim3 tb(32, 8);
    wtrans_kernel<<<dim3(BDIM / 32, BDIM / 32), tb>>>(Wq, wq_h, wq_l, BDIM, BDIM);
    wtrans_kernel<<<dim3(BDIM / 32, BDIM / 32), tb>>>(Wk, wk_h, wk_l, BDIM, BDIM);
    wtrans_kernel<<<dim3(BDIM / 32, BDIM / 32), tb>>>(Wv, wv_h, wv_l, BDIM, BDIM);
    wtrans_kernel<<<dim3(BDIM / 32, BDIM / 32), tb>>>(Wo, wo_h, wo_l, BDIM, BDIM);
    wtrans_kernel<<<dim3(HIDN / 32, BDIM / 32), tb>>>(W1, w1_h, w1_l, BDIM, HIDN);
    wtrans_kernel<<<dim3(BDIM / 32, HIDN / 32), tb>>>(W2, w2_h, w2_l, HIDN, BDIM);

    // ---- activation splits ----
    cvt_hilo<<<(MROWS * BDIM) / 1024, 256>>>(x, xhi, xlo);
    cvt_hilo<<<(MROWS * BDIM) / 1024, 256>>>(y, yhi, ylo);

    dim3 gD(BDIM / 128, MROWS / 128);
    dim3 gH(HIDN / 128, MROWS / 128);

    // QKV projections -> [B,H,S,DK] fp32
    mma_gemm<<<gD, 256, GEMM_SMEM>>>(xhi, xlo, wq_h, wq_l, bq, nullptr, Qp, nullptr, nullptr, MROWS, BDIM, BDIM, MODE_SPLIT);
    mma_gemm<<<gD, 256, GEMM_SMEM>>>(yhi, ylo, wk_h, wk_l, bk, nullptr, Kp, nullptr, nullptr, MROWS, BDIM, BDIM, MODE_SPLIT);
    mma_gemm<<<gD, 256, GEMM_SMEM>>>(yhi, ylo, wv_h, wv_l, bv, nullptr, Vp, nullptr, nullptr, MROWS, BDIM, BDIM, MODE_SPLIT);

    // fused attention -> bf16 hi/lo in [B,S,D]
    size_t shm = (size_t)(4 * 64 * AST) * sizeof(float) + 64 * sizeof(int);
    cudaFuncSetAttribute(attn_kernel, cudaFuncAttributeMaxDynamicSharedMemorySize, (int)shm);
    attn_kernel<<<dim3(SEQ / 64, NH, NB), 256, shm>>>(Qp, Kp, Vp, mask, ahi, alo);

    // s1 = x + attn @ Wo + bo ; x1 = LN(s1) (+hi/lo)
    mma_gemm<<<gD, 256, GEMM_SMEM>>>(ahi, alo, wo_h, wo_l, bo, x, s1p, nullptr, nullptr, MROWS, BDIM, BDIM, MODE_RES);
    ln_kernel<<<MROWS, 256>>>(s1p, g1, be1, x1p, x1hi, x1lo);

    // FFN
    mma_gemm<<<gH, 256, GEMM_SMEM>>>(x1hi, x1lo, w1_h, w1_l, b1, nullptr, nullptr, hhi, hlo, MROWS, HIDN, BDIM, MODE_RELU_HL);
    mma_gemm<<<gD, 256, GEMM_SMEM>>>(hhi, hlo, w2_h, w2_l, b2, x1p, s2p, nullptr, nullptr, MROWS, BDIM, HIDN, MODE_RES);
    ln_kernel<<<MROWS, 256>>>(s2p, g2, be2, out, nullptr, nullptr);
}

// round 7
// speedup vs baseline: 2.3849x; 1.6087x over previous
#include <cuda_runtime.h>
#include <cuda_bf16.h>
#include <math.h>
#include <stdint.h>

#define BDIM 1024
#define SEQ  2048
#define NH   16
#define DKH  64
#define HIDN 4096
#define MROWS 4096   // B*S
#define NB   2

typedef __nv_bfloat16 bf16;

// ---------------- scratch (static device globals; no allocation) ----------------
__device__ float g_s1 [MROWS * BDIM];
__device__ float g_x1 [MROWS * BDIM];
__device__ float g_s2 [MROWS * BDIM];

__device__ bf16 g_xhi [MROWS * BDIM];
__device__ bf16 g_xlo [MROWS * BDIM];
__device__ bf16 g_yhi [MROWS * BDIM];
__device__ bf16 g_ylo [MROWS * BDIM];
__device__ bf16 g_Qhi [MROWS * BDIM];   // [B,H,S,DK]
__device__ bf16 g_Qlo [MROWS * BDIM];
__device__ bf16 g_Khi [MROWS * BDIM];
__device__ bf16 g_Klo [MROWS * BDIM];
__device__ bf16 g_Vb  [MROWS * BDIM];
__device__ bf16 g_ahi [MROWS * BDIM];   // attention output [B,S,D]
__device__ bf16 g_alo [MROWS * BDIM];
__device__ bf16 g_x1hi[MROWS * BDIM];
__device__ bf16 g_x1lo[MROWS * BDIM];
__device__ bf16 g_hhi [MROWS * HIDN];
__device__ bf16 g_hlo [MROWS * HIDN];

// transposed + split weights: Wt[N][K]
__device__ bf16 g_wqT_hi[BDIM * BDIM], g_wqT_lo[BDIM * BDIM];
__device__ bf16 g_wkT_hi[BDIM * BDIM], g_wkT_lo[BDIM * BDIM];
__device__ bf16 g_wvT_hi[BDIM * BDIM], g_wvT_lo[BDIM * BDIM];
__device__ bf16 g_woT_hi[BDIM * BDIM], g_woT_lo[BDIM * BDIM];
__device__ bf16 g_w1T_hi[HIDN * BDIM], g_w1T_lo[HIDN * BDIM];
__device__ bf16 g_w2T_hi[BDIM * HIDN], g_w2T_lo[BDIM * HIDN];

enum { MODE_RELU_HL = 1, MODE_RES = 2, MODE_SPLIT_HL = 3, MODE_SPLIT_V = 4 };

// ======================= PTX helpers =======================
__device__ __forceinline__ uint32_t smem_u32(const void* p) {
    uint32_t a;
    asm("{ .reg .u64 t; cvta.to.shared.u64 t, %1; cvt.u32.u64 %0, t; }" : "=r"(a) : "l"(p));
    return a;
}
__device__ __forceinline__ void cp16(uint32_t s, const void* g) {
    asm volatile("cp.async.cg.shared.global [%0], [%1], 16;" :: "r"(s), "l"(g));
}
#define CP_COMMIT() asm volatile("cp.async.commit_group;" ::: "memory")
#define CP_WAIT0()  asm volatile("cp.async.wait_group 0;" ::: "memory")
#define CP_WAIT1()  asm volatile("cp.async.wait_group 1;" ::: "memory")

__device__ __forceinline__ void ldm_x4(uint32_t& r0, uint32_t& r1, uint32_t& r2, uint32_t& r3, uint32_t a) {
    asm volatile("ldmatrix.sync.aligned.m8n8.x4.shared.b16 {%0,%1,%2,%3}, [%4];"
                 : "=r"(r0), "=r"(r1), "=r"(r2), "=r"(r3) : "r"(a));
}
__device__ __forceinline__ void ldm_x4_t(uint32_t& r0, uint32_t& r1, uint32_t& r2, uint32_t& r3, uint32_t a) {
    asm volatile("ldmatrix.sync.aligned.m8n8.x4.trans.shared.b16 {%0,%1,%2,%3}, [%4];"
                 : "=r"(r0), "=r"(r1), "=r"(r2), "=r"(r3) : "r"(a));
}
__device__ __forceinline__ void mma16816(float* c, const uint32_t* a, const uint32_t* b) {
    asm volatile("mma.sync.aligned.m16n8k16.row.col.f32.bf16.bf16.f32 "
                 "{%0,%1,%2,%3}, {%4,%5,%6,%7}, {%8,%9}, {%0,%1,%2,%3};"
                 : "+f"(c[0]), "+f"(c[1]), "+f"(c[2]), "+f"(c[3])
                 : "r"(a[0]), "r"(a[1]), "r"(a[2]), "r"(a[3]), "r"(b[0]), "r"(b[1]));
}
__device__ __forceinline__ uint32_t cvt2(float a, float b) {
    __nv_bfloat162 t = __floats2bfloat162_rn(a, b);
    return *(uint32_t*)&t;
}

// ======================= mma.sync bf16 split-precision GEMM =======================
#define BK 32
#define APAD 40
#define TILE_B (128 * APAD * 2)
#define SLAB_B (4 * TILE_B)
#define GEMM_SMEM (2 * SLAB_B)

__global__ __launch_bounds__(256, 1) void mma_gemm(
    const bf16* __restrict__ Ahi, const bf16* __restrict__ Alo,
    const bf16* __restrict__ Bhi, const bf16* __restrict__ Blo,
    const float* __restrict__ bias, const float* __restrict__ R,
    float* __restrict__ outF, bf16* __restrict__ outHi, bf16* __restrict__ outLo,
    int M, int N, int K, int mode)
{
    extern __shared__ char sm[];
    const uint32_t smb = smem_u32(sm);
    const int tid = threadIdx.x;
    const int wid = tid >> 5;
    const int lid = tid & 31;
    const int warp_m = wid >> 2;
    const int warp_n = wid & 3;
    const int row0 = blockIdx.y * 128;
    const int col0 = blockIdx.x * 128;

    const bf16* src[4];
    src[0] = Ahi + (size_t)row0 * K;
    src[1] = Alo + (size_t)row0 * K;
    src[2] = Bhi + (size_t)col0 * K;
    src[3] = Blo + (size_t)col0 * K;

    const int NS = K / BK;

#define LOAD_SLAB(ST, KS) do {                                                \
        const uint32_t _sb = smb + (ST) * SLAB_B;                             \
        const int _ko = (KS) * BK;                                            \
        _Pragma("unroll")                                                     \
        for (int t = 0; t < 4; t++) {                                         \
            const bf16* g = src[t] + _ko;                                     \
            const uint32_t tb = _sb + t * TILE_B;                             \
            _Pragma("unroll")                                                 \
            for (int u = 0; u < 2; u++) {                                     \
                int p = tid + u * 256;                                        \
                int r = p >> 2, c = p & 3;                                    \
                cp16(tb + (uint32_t)(r * (APAD * 2) + c * 16),                \
                     g + (size_t)r * K + c * 8);                              \
            }                                                                 \
        }                                                                     \
        CP_COMMIT();                                                          \
    } while (0)

    float acc[4][4][4];
#pragma unroll
    for (int i = 0; i < 4; i++)
#pragma unroll
        for (int j = 0; j < 4; j++)
#pragma unroll
            for (int f = 0; f < 4; f++) acc[i][j][f] = 0.f;

    LOAD_SLAB(0, 0);

    const uint32_t lrow = (uint32_t)(lid & 15);
    const uint32_t lcol16 = (uint32_t)(lid >> 4) * 16;

    for (int s = 0; s < NS; s++) {
        const int st = s & 1;
        if (s + 1 < NS) { LOAD_SLAB(st ^ 1, s + 1); CP_WAIT1(); }
        else            { CP_WAIT0(); }
        __syncthreads();

        const uint32_t sb  = smb + st * SLAB_B;
        const uint32_t ab_hi = sb;
        const uint32_t ab_lo = sb + TILE_B;
        const uint32_t bb_hi = sb + 2 * TILE_B;
        const uint32_t bb_lo = sb + 3 * TILE_B;

#pragma unroll
        for (int kk = 0; kk < 2; kk++) {
            const uint32_t koff = kk * 32 + lcol16;

            uint32_t ah[4][4], al[4][4];
#pragma unroll
            for (int mi = 0; mi < 4; mi++) {
                uint32_t ra = (uint32_t)((warp_m * 64 + mi * 16 + lrow) * (APAD * 2)) + koff;
                ldm_x4(ah[mi][0], ah[mi][1], ah[mi][2], ah[mi][3], ab_hi + ra);
                ldm_x4(al[mi][0], al[mi][1], al[mi][2], al[mi][3], ab_lo + ra);
            }
            uint32_t bh[4][2], bl[4][2];
#pragma unroll
            for (int nt = 0; nt < 2; nt++) {
                uint32_t rb = (uint32_t)((warp_n * 32 + nt * 16 + lrow) * (APAD * 2)) + koff;
                uint32_t r0, r1, r2, r3;
                ldm_x4(r0, r1, r2, r3, bb_hi + rb);
                bh[nt * 2 + 0][0] = r0; bh[nt * 2 + 0][1] = r2;
                bh[nt * 2 + 1][0] = r1; bh[nt * 2 + 1][1] = r3;
                ldm_x4(r0, r1, r2, r3, bb_lo + rb);
                bl[nt * 2 + 0][0] = r0; bl[nt * 2 + 0][1] = r2;
                bl[nt * 2 + 1][0] = r1; bl[nt * 2 + 1][1] = r3;
            }
#pragma unroll
            for (int mi = 0; mi < 4; mi++)
#pragma unroll
                for (int ni = 0; ni < 4; ni++) {
                    mma16816(acc[mi][ni], ah[mi], bh[ni]);
                    mma16816(acc[mi][ni], ah[mi], bl[ni]);
                    mma16816(acc[mi][ni], al[mi], bh[ni]);
                }
        }
        __syncthreads();
    }

    // ---- epilogue ----
    const int qr = lid >> 2;
    const int qc = (lid & 3) * 2;
#pragma unroll
    for (int mi = 0; mi < 4; mi++) {
#pragma unroll
        for (int ni = 0; ni < 4; ni++) {
            const int n = col0 + warp_n * 32 + ni * 8 + qc;
            const float b0 = bias[n], b1 = bias[n + 1];
#pragma unroll
            for (int half = 0; half < 2; half++) {
                const int m = row0 + warp_m * 64 + mi * 16 + qr + half * 8;
                float v0 = acc[mi][ni][half * 2 + 0] + b0;
                float v1 = acc[mi][ni][half * 2 + 1] + b1;
                if (mode == MODE_RES) {
                    const float* rp = &R[(size_t)m * N + n];
                    v0 += rp[0]; v1 += rp[1];
                    float2 o2 = {v0, v1};
                    *(float2*)&outF[(size_t)m * N + n] = o2;
                } else if (mode == MODE_SPLIT_HL || mode == MODE_SPLIT_V) {
                    int hh = n >> 6, dk = n & 63, bb = m >> 11, ss = m & 2047;
                    size_t o = (((size_t)(bb * NH + hh)) * SEQ + ss) * DKH + dk;
                    bf16 h0 = __float2bfloat16(v0), h1 = __float2bfloat16(v1);
                    __nv_bfloat162 p; p.x = h0; p.y = h1;
                    *(__nv_bfloat162*)&outHi[o] = p;
                    if (mode == MODE_SPLIT_HL) {
                        p.x = __float2bfloat16(v0 - __bfloat162float(h0));
                        p.y = __float2bfloat16(v1 - __bfloat162float(h1));
                        *(__nv_bfloat162*)&outLo[o] = p;
                    }
                } else { // MODE_RELU_HL
                    v0 = fmaxf(v0, 0.f); v1 = fmaxf(v1, 0.f);
                    bf16 h0 = __float2bfloat16(v0), h1 = __float2bfloat16(v1);
                    __nv_bfloat162 p; p.x = h0; p.y = h1;
                    *(__nv_bfloat162*)&outHi[(size_t)m * N + n] = p;
                    p.x = __float2bfloat16(v0 - __bfloat162float(h0));
                    p.y = __float2bfloat16(v1 - __bfloat162float(h1));
                    *(__nv_bfloat162*)&outLo[(size_t)m * N + n] = p;
                }
            }
        }
    }
}

// ======================= tensor-core flash attention =======================
// Q/K bf16 hi+lo, V bf16, all [B,H,S,DK]. CTA = 128 queries x 1 head.
// 8 warps x 16 queries. KV tile 64, double-buffered cp.async.
// smem row stride = 72 bf16 = 144B (144 % 128 == 16 -> conflict-free ldmatrix).
#define AT_STRIDE 144
#define AT_TILE   (64 * AT_STRIDE)            // 9216 B per 64x64 bf16 tile
#define AT_STAGE  (3 * AT_TILE)               // Khi, Klo, V
#define AT_MSK    (2 * AT_STAGE)              // 55296
#define AT_SMEM   (AT_MSK + 512)

__global__ __launch_bounds__(256, 1) void attn_tc(
    const bf16* __restrict__ Qhi, const bf16* __restrict__ Qlo,
    const bf16* __restrict__ Khi, const bf16* __restrict__ Klo,
    const bf16* __restrict__ Vb, const int* __restrict__ mask,
    bf16* __restrict__ Ohi, bf16* __restrict__ Olo)
{
    extern __shared__ char sm[];
    const uint32_t smb = smem_u32(sm);
    const int tid = threadIdx.x;
    const int wid = tid >> 5;
    const int lid = tid & 31;
    const int q0  = blockIdx.x * 128;
    const int h   = blockIdx.y;
    const int bz  = blockIdx.z;
    const size_t hoff = ((size_t)(bz * NH + h)) * SEQ * DKH;

    const uint32_t lr   = (uint32_t)(lid & 15);
    const uint32_t lc16 = (uint32_t)(lid >> 4) * 16;

    // ---- Q tile -> smem (hi @0, lo @18432), then register fragments ----
    {
        const bf16* qh = Qhi + hoff + (size_t)q0 * DKH;
        const bf16* ql = Qlo + hoff + (size_t)q0 * DKH;
#pragma unroll
        for (int u = 0; u < 4; u++) {
            int p = tid + u * 256;
            int r = p >> 3, c = p & 7;
            cp16(smb + (uint32_t)(r * AT_STRIDE + c * 16), qh + (size_t)r * DKH + c * 8);
            cp16(smb + 18432u + (uint32_t)(r * AT_STRIDE + c * 16), ql + (size_t)r * DKH + c * 8);
        }
        CP_COMMIT(); CP_WAIT0();
    }
    __syncthreads();
    uint32_t qfh[4][4], qfl[4][4];
#pragma unroll
    for (int ks = 0; ks < 4; ks++) {
        uint32_t ra = (uint32_t)((wid * 16 + lr) * AT_STRIDE) + ks * 32 + lc16;
        ldm_x4(qfh[ks][0], qfh[ks][1], qfh[ks][2], qfh[ks][3], smb + ra);
        ldm_x4(qfl[ks][0], qfl[ks][1], qfl[ks][2], qfl[ks][3], smb + 18432u + ra);
    }
    __syncthreads();

    float O[8][4];
#pragma unroll
    for (int i = 0; i < 8; i++)
#pragma unroll
        for (int j = 0; j < 4; j++) O[i][j] = 0.f;
    float m0 = -INFINITY, m1 = -INFINITY, l0 = 0.f, l1 = 0.f;

    const bf16* khg = Khi + hoff;
    const bf16* klg = Klo + hoff;
    const bf16* vg  = Vb  + hoff;
    const int*  mkg = mask + bz * SEQ;

#define LOAD_KV(ST, T) do {                                                     \
        const uint32_t _sb = smb + (ST) * AT_STAGE;                             \
        const int _k0 = (T) * 64;                                               \
        _Pragma("unroll")                                                       \
        for (int u = 0; u < 2; u++) {                                           \
            int p = tid + u * 256;                                              \
            int r = p >> 3, c = p & 7;                                          \
            uint32_t so = (uint32_t)(r * AT_STRIDE + c * 16);                   \
            size_t go = (size_t)(_k0 + r) * DKH + c * 8;                        \
            cp16(_sb + so, khg + go);                                           \
            cp16(_sb + AT_TILE + so, klg + go);                                 \
            cp16(_sb + 2 * AT_TILE + so, vg + go);                              \
        }                                                                       \
        if (tid < 16) cp16(smb + AT_MSK + (ST) * 256 + tid * 16, mkg + _k0 + tid * 4); \
        CP_COMMIT();                                                            \
    } while (0)

    LOAD_KV(0, 0);

    for (int t = 0; t < SEQ / 64; t++) {
        const int st = t & 1;
        if (t + 1 < SEQ / 64) { LOAD_KV(st ^ 1, t + 1); CP_WAIT1(); }
        else                  { CP_WAIT0(); }
        __syncthreads();

        const uint32_t sb = smb + st * AT_STAGE;
        const int* msk = (const int*)(sm + AT_MSK + st * 256);

        // ---- scores: 3-pass split QK^T ----
        float s[8][4];
#pragma unroll
        for (int i = 0; i < 8; i++)
#pragma unroll
            for (int j = 0; j < 4; j++) s[i][j] = 0.f;

#pragma unroll
        for (int ks = 0; ks < 4; ks++) {
            const uint32_t koff = ks * 32 + lc16;
#pragma unroll
            for (int g = 0; g < 4; g++) {
                uint32_t rb = (uint32_t)((g * 16 + lr) * AT_STRIDE) + koff;
                uint32_t r0, r1, r2, r3;
                ldm_x4(r0, r1, r2, r3, sb + rb);
                uint32_t bh0[2] = {r0, r2}, bh1[2] = {r1, r3};
                ldm_x4(r0, r1, r2, r3, sb + AT_TILE + rb);
                uint32_t bl0[2] = {r0, r2}, bl1[2] = {r1, r3};
                mma16816(s[2 * g],     qfh[ks], bh0);
                mma16816(s[2 * g + 1], qfh[ks], bh1);
                mma16816(s[2 * g],     qfh[ks], bl0);
                mma16816(s[2 * g + 1], qfh[ks], bl1);
                mma16816(s[2 * g],     qfl[ks], bh0);
                mma16816(s[2 * g + 1], qfl[ks], bh1);
            }
        }

        // ---- mask + scale ----
#pragma unroll
        for (int j = 0; j < 8; j++) {
            int c0 = j * 8 + (lid & 3) * 2;
            bool z0 = (msk[c0] == 0), z1 = (msk[c0 + 1] == 0);
            s[j][0] = z0 ? -1e9f : s[j][0] * 0.125f;
            s[j][2] = z0 ? -1e9f : s[j][2] * 0.125f;
            s[j][1] = z1 ? -1e9f : s[j][1] * 0.125f;
            s[j][3] = z1 ? -1e9f : s[j][3] * 0.125f;
        }

        // ---- online softmax (rows r and r+8) ----
        float mx0 = -INFINITY, mx1 = -INFINITY;
#pragma unroll
        for (int j = 0; j < 8; j++) {
            mx0 = fmaxf(mx0, fmaxf(s[j][0], s[j][1]));
            mx1 = fmaxf(mx1, fmaxf(s[j][2], s[j][3]));
        }
#pragma unroll
        for (int off = 1; off <= 2; off <<= 1) {
            mx0 = fmaxf(mx0, __shfl_xor_sync(0xffffffffu, mx0, off));
            mx1 = fmaxf(mx1, __shfl_xor_sync(0xffffffffu, mx1, off));
        }
        float nm0 = fmaxf(m0, mx0), nm1 = fmaxf(m1, mx1);
        float a0 = __expf(m0 - nm0), a1 = __expf(m1 - nm1);
        float sum0 = 0.f, sum1 = 0.f;
#pragma unroll
        for (int j = 0; j < 8; j++) {
            s[j][0] = __expf(s[j][0] - nm0); sum0 += s[j][0];
            s[j][1] = __expf(s[j][1] - nm0); sum0 += s[j][1];
            s[j][2] = __expf(s[j][2] - nm1); sum1 += s[j][2];
            s[j][3] = __expf(s[j][3] - nm1); sum1 += s[j][3];
        }
#pragma unroll
        for (int off = 1; off <= 2; off <<= 1) {
            sum0 += __shfl_xor_sync(0xffffffffu, sum0, off);
            sum1 += __shfl_xor_sync(0xffffffffu, sum1, off);
        }
        l0 = l0 * a0 + sum0;
        l1 = l1 * a1 + sum1;
        m0 = nm0; m1 = nm1;
#pragma unroll
        for (int i = 0; i < 8; i++) {
            O[i][0] *= a0; O[i][1] *= a0;
            O[i][2] *= a1; O[i][3] *= a1;
        }

        // ---- O += P @ V (P from registers, V via ldmatrix.trans) ----
#pragma unroll
        for (int j = 0; j < 4; j++) {
            uint32_t P[4];
            P[0] = cvt2(s[2 * j][0],     s[2 * j][1]);
            P[1] = cvt2(s[2 * j][2],     s[2 * j][3]);
            P[2] = cvt2(s[2 * j + 1][0], s[2 * j + 1][1]);
            P[3] = cvt2(s[2 * j + 1][2], s[2 * j + 1][3]);
#pragma unroll
            for (int c = 0; c < 4; c++) {
                uint32_t r0, r1, r2, r3;
                ldm_x4_t(r0, r1, r2, r3,
                         sb + 2 * AT_TILE + (uint32_t)((j * 16 + lr) * AT_STRIDE) + c * 32 + lc16);
                uint32_t B0[2] = {r0, r1}, B1[2] = {r2, r3};
                mma16816(O[2 * c],     P, B0);
                mma16816(O[2 * c + 1], P, B1);
            }
        }
        __syncthreads();
    }

    // ---- epilogue: normalize, hi/lo split, write [B,S,D] ----
    const float il0 = 1.f / (l0 > 0.f ? l0 : 1.f);
    const float il1 = 1.f / (l1 > 0.f ? l1 : 1.f);
    const int qr  = q0 + wid * 16 + (lid >> 2);
    const int col0 = h * DKH + (lid & 3) * 2;
#pragma unroll
    for (int nt = 0; nt < 8; nt++) {
        const int col = col0 + nt * 8;
        {
            float v0 = O[nt][0] * il0, v1 = O[nt][1] * il0;
            size_t o = ((size_t)bz * SEQ + qr) * BDIM + col;
            bf16 h0 = __float2bfloat16(v0), h1 = __float2bfloat16(v1);
            __nv_bfloat162 p; p.x = h0; p.y = h1;
            *(__nv_bfloat162*)&Ohi[o] = p;
            p.x = __float2bfloat16(v0 - __bfloat162float(h0));
            p.y = __float2bfloat16(v1 - __bfloat162float(h1));
            *(__nv_bfloat162*)&Olo[o] = p;
        }
        {
            float v0 = O[nt][2] * il1, v1 = O[nt][3] * il1;
            size_t o = ((size_t)bz * SEQ + qr + 8) * BDIM + col;
            bf16 h0 = __float2bfloat16(v0), h1 = __float2bfloat16(v1);
            __nv_bfloat162 p; p.x = h0; p.y = h1;
            *(__nv_bfloat162*)&Ohi[o] = p;
            p.x = __float2bfloat16(v0 - __bfloat162float(h0));
            p.y = __float2bfloat16(v1 - __bfloat162float(h1));
            *(__nv_bfloat162*)&Olo[o] = p;
        }
    }
}

// ======================= weight transpose + hi/lo split =======================
__global__ __launch_bounds__(256) void wtrans_kernel(
    const float* __restrict__ W, bf16* __restrict__ hiT, bf16* __restrict__ loT,
    int K, int N)
{
    __shared__ float t[32][33];
    const int n0 = blockIdx.x * 32, k0 = blockIdx.y * 32;
    const int tx = threadIdx.x, ty = threadIdx.y;
#pragma unroll
    for (int j = 0; j < 4; j++)
        t[ty + j * 8][tx] = W[(size_t)(k0 + ty + j * 8) * N + n0 + tx];
    __syncthreads();
#pragma unroll
    for (int j = 0; j < 4; j++) {
        float v = t[tx][ty + j * 8];
        bf16 h = __float2bfloat16(v);
        size_t o = (size_t)(n0 + ty + j * 8) * K + k0 + tx;
        hiT[o] = h;
        loT[o] = __float2bfloat16(v - __bfloat162float(h));
    }
}

// ======================= fp32 -> hi/lo split =======================
__global__ __launch_bounds__(256) void cvt_hilo(
    const float* __restrict__ X, bf16* __restrict__ hi, bf16* __restrict__ lo)
{
    const int i = (blockIdx.x * 256 + threadIdx.x) * 4;
    const float4 v = *(const float4*)(X + i);
    bf16 h0 = __float2bfloat16(v.x), h1 = __float2bfloat16(v.y);
    bf16 h2 = __float2bfloat16(v.z), h3 = __float2bfloat16(v.w);
    __nv_bfloat162 a, b;
    a.x = h0; a.y = h1; b.x = h2; b.y = h3;
    *(__nv_bfloat162*)(hi + i)     = a;
    *(__nv_bfloat162*)(hi + i + 2) = b;
    a.x = __float2bfloat16(v.x - __bfloat162float(h0));
    a.y = __float2bfloat16(v.y - __bfloat162float(h1));
    b.x = __float2bfloat16(v.z - __bfloat162float(h2));
    b.y = __float2bfloat16(v.w - __bfloat162float(h3));
    *(__nv_bfloat162*)(lo + i)     = a;
    *(__nv_bfloat162*)(lo + i + 2) = b;
}

// ======================= LayerNorm (+ optional hi/lo output) =======================
__global__ __launch_bounds__(256) void ln_kernel(
    const float* __restrict__ X, const float* __restrict__ g,
    const float* __restrict__ b, float* __restrict__ Y,
    bf16* __restrict__ Yhi, bf16* __restrict__ Ylo)
{
    __shared__ float red[2][8];
    __shared__ float stats[2];
    const int row = blockIdx.x;
    const int tid = threadIdx.x;

    const float4 v = ((const float4*)(X + (size_t)row * BDIM))[tid];
    float s = v.x + v.y + v.z + v.w;
    float q = v.x * v.x + v.y * v.y + v.z * v.z + v.w * v.w;
#pragma unroll
    for (int o = 16; o > 0; o >>= 1) {
        s += __shfl_xor_sync(0xffffffffu, s, o);
        q += __shfl_xor_sync(0xffffffffu, q, o);
    }
    const int lane = tid & 31, w = tid >> 5;
    if (lane == 0) { red[0][w] = s; red[1][w] = q; }
    __syncthreads();
    if (tid < 32) {
        s = (tid < 8) ? red[0][tid] : 0.f;
        q = (tid < 8) ? red[1][tid] : 0.f;
#pragma unroll
        for (int o = 4; o > 0; o >>= 1) {
            s += __shfl_xor_sync(0xffffffffu, s, o);
            q += __shfl_xor_sync(0xffffffffu, q, o);
        }
        if (tid == 0) {
            float mean = s * (1.f / BDIM);
            stats[0] = mean;
            stats[1] = rsqrtf(q * (1.f / BDIM) - mean * mean + 1e-5f);
        }
    }
    __syncthreads();
    const float mean = stats[0], rinv = stats[1];
    const float4 gg = ((const float4*)g)[tid];
    const float4 bb = ((const float4*)b)[tid];
    float4 o4;
    o4.x = (v.x - mean) * rinv * gg.x + bb.x;
    o4.y = (v.y - mean) * rinv * gg.y + bb.y;
    o4.z = (v.z - mean) * rinv * gg.z + bb.z;
    o4.w = (v.w - mean) * rinv * gg.w + bb.w;
    if (Y) ((float4*)(Y + (size_t)row * BDIM))[tid] = o4;
    if (Yhi) {
        size_t base = (size_t)row * BDIM + tid * 4;
        bf16 h0 = __float2bfloat16(o4.x), h1 = __float2bfloat16(o4.y);
        bf16 h2 = __float2bfloat16(o4.z), h3 = __float2bfloat16(o4.w);
        __nv_bfloat162 p;
        p.x = h0; p.y = h1; *(__nv_bfloat162*)(Yhi + base)     = p;
        p.x = h2; p.y = h3; *(__nv_bfloat162*)(Yhi + base + 2) = p;
        p.x = __float2bfloat16(o4.x - __bfloat162float(h0));
        p.y = __float2bfloat16(o4.y - __bfloat162float(h1));
        *(__nv_bfloat162*)(Ylo + base) = p;
        p.x = __float2bfloat16(o4.z - __bfloat162float(h2));
        p.y = __float2bfloat16(o4.w - __bfloat162float(h3));
        *(__nv_bfloat162*)(Ylo + base + 2) = p;
    }
}

// ======================= launcher =======================
extern "C" void kernel_launch(void* const* d_in, const int* in_sizes, int n_in,
                              void* d_out, int out_size)
{
    const float* x    = (const float*)d_in[0];
    const float* y    = (const float*)d_in[1];
    const int*   mask = (const int*)  d_in[2];
    const float* Wq = (const float*)d_in[3];  const float* bq = (const float*)d_in[4];
    const float* Wk = (const float*)d_in[5];  const float* bk = (const float*)d_in[6];
    const float* Wv = (const float*)d_in[7];  const float* bv = (const float*)d_in[8];
    const float* Wo = (const float*)d_in[9];  const float* bo = (const float*)d_in[10];
    const float* W1 = (const float*)d_in[11]; const float* b1 = (const float*)d_in[12];
    const float* W2 = (const float*)d_in[13]; const float* b2 = (const float*)d_in[14];
    const float* g1 = (const float*)d_in[15]; const float* be1 = (const float*)d_in[16];
    const float* g2 = (const float*)d_in[17]; const float* be2 = (const float*)d_in[18];
    float* out = (float*)d_out;

    float *s1p, *x1p, *s2p;
    bf16 *xhi, *xlo, *yhi, *ylo, *qhi, *qlo, *khi, *klo, *vb;
    bf16 *ahi, *alo, *x1hi, *x1lo, *hhi, *hlo;
    bf16 *wq_h, *wq_l, *wk_h, *wk_l, *wv_h, *wv_l, *wo_h, *wo_l, *w1_h, *w1_l, *w2_h, *w2_l;
    cudaGetSymbolAddress((void**)&s1p, g_s1);  cudaGetSymbolAddress((void**)&x1p, g_x1);
    cudaGetSymbolAddress((void**)&s2p, g_s2);
    cudaGetSymbolAddress((void**)&xhi, g_xhi); cudaGetSymbolAddress((void**)&xlo, g_xlo);
    cudaGetSymbolAddress((void**)&yhi, g_yhi); cudaGetSymbolAddress((void**)&ylo, g_ylo);
    cudaGetSymbolAddress((void**)&qhi, g_Qhi); cudaGetSymbolAddress((void**)&qlo, g_Qlo);
    cudaGetSymbolAddress((void**)&khi, g_Khi); cudaGetSymbolAddress((void**)&klo, g_Klo);
    cudaGetSymbolAddress((void**)&vb,  g_Vb);
    cudaGetSymbolAddress((void**)&ahi, g_ahi); cudaGetSymbolAddress((void**)&alo, g_alo);
    cudaGetSymbolAddress((void**)&x1hi, g_x1hi); cudaGetSymbolAddress((void**)&x1lo, g_x1lo);
    cudaGetSymbolAddress((void**)&hhi, g_hhi); cudaGetSymbolAddress((void**)&hlo, g_hlo);
    cudaGetSymbolAddress((void**)&wq_h, g_wqT_hi); cudaGetSymbolAddress((void**)&wq_l, g_wqT_lo);
    cudaGetSymbolAddress((void**)&wk_h, g_wkT_hi); cudaGetSymbolAddress((void**)&wk_l, g_wkT_lo);
    cudaGetSymbolAddress((void**)&wv_h, g_wvT_hi); cudaGetSymbolAddress((void**)&wv_l, g_wvT_lo);
    cudaGetSymbolAddress((void**)&wo_h, g_woT_hi); cudaGetSymbolAddress((void**)&wo_l, g_woT_lo);
    cudaGetSymbolAddress((void**)&w1_h, g_w1T_hi); cudaGetSymbolAddress((void**)&w1_l, g_w1T_lo);
    cudaGetSymbolAddress((void**)&w2_h, g_w2T_hi); cudaGetSymbolAddress((void**)&w2_l, g_w2T_lo);

    cudaFuncSetAttribute(mma_gemm, cudaFuncAttributeMaxDynamicSharedMemorySize, GEMM_SMEM);
    cudaFuncSetAttribute(attn_tc,  cudaFuncAttributeMaxDynamicSharedMemorySize, AT_SMEM);

    // ---- weight prep ----
    dim3 tb(32, 8);
    wtrans_kernel<<<dim3(BDIM / 32, BDIM / 32), tb>>>(Wq, wq_h, wq_l, BDIM, BDIM);
    wtrans_kernel<<<dim3(BDIM / 32, BDIM / 32), tb>>>(Wk, wk_h, wk_l, BDIM, BDIM);
    wtrans_kernel<<<dim3(BDIM / 32, BDIM / 32), tb>>>(Wv, wv_h, wv_l, BDIM, BDIM);
    wtrans_kernel<<<dim3(BDIM / 32, BDIM / 32), tb>>>(Wo, wo_h, wo_l, BDIM, BDIM);
    wtrans_kernel<<<dim3(HIDN / 32, BDIM / 32), tb>>>(W1, w1_h, w1_l, BDIM, HIDN);
    wtrans_kernel<<<dim3(BDIM / 32, HIDN / 32), tb>>>(W2, w2_h, w2_l, HIDN, BDIM);

    // ---- activation splits ----
    cvt_hilo<<<(MROWS * BDIM) / 1024, 256>>>(x, xhi, xlo);
    cvt_hilo<<<(MROWS * BDIM) / 1024, 256>>>(y, yhi, ylo);

    dim3 gD(BDIM / 128, MROWS / 128);
    dim3 gH(HIDN / 128, MROWS / 128);

    // QKV projections -> bf16 hi/lo [B,H,S,DK]
    mma_gemm<<<gD, 256, GEMM_SMEM>>>(xhi, xlo, wq_h, wq_l, bq, nullptr, nullptr, qhi, qlo, MROWS, BDIM, BDIM, MODE_SPLIT_HL);
    mma_gemm<<<gD, 256, GEMM_SMEM>>>(yhi, ylo, wk_h, wk_l, bk, nullptr, nullptr, khi, klo, MROWS, BDIM, BDIM, MODE_SPLIT_HL);
    mma_gemm<<<gD, 256, GEMM_SMEM>>>(yhi, ylo, wv_h, wv_l, bv, nullptr, nullptr, vb,  nullptr, MROWS, BDIM, BDIM, MODE_SPLIT_V);

    // tensor-core flash attention -> bf16 hi/lo [B,S,D]
    attn_tc<<<dim3(SEQ / 128, NH, NB), 256, AT_SMEM>>>(qhi, qlo, khi, klo, vb, mask, ahi, alo);

    // s1 = x + attn @ Wo + bo ; x1 = LN(s1) (+hi/lo)
    mma_gemm<<<gD, 256, GEMM_SMEM>>>(ahi, alo, wo_h, wo_l, bo, x, s1p, nullptr, nullptr, MROWS, BDIM, BDIM, MODE_RES);
    ln_kernel<<<MROWS, 256>>>(s1p, g1, be1, x1p, x1hi, x1lo);

    // FFN
    mma_gemm<<<gH, 256, GEMM_SMEM>>>(x1hi, x1lo, w1_h, w1_l, b1, nullptr, nullptr, hhi, hlo, MROWS, HIDN, BDIM, MODE_RELU_HL);
    mma_gemm<<<gD, 256, GEMM_SMEM>>>(hhi, hlo, w2_h, w2_l, b2, x1p, s2p, nullptr, nullptr, MROWS, BDIM, HIDN, MODE_RES);
    ln_kernel<<<MROWS, 256>>>(s2p, g2, be2, out, nullptr, nullptr);
}

// round 8
// speedup vs baseline: 3.5265x; 1.4787x over previous
#include <cuda_runtime.h>
#include <cuda_fp16.h>
#include <math.h>
#include <stdint.h>

#define BDIM 1024
#define SEQ  2048
#define NH   16
#define DKH  64
#define HIDN 4096
#define MROWS 4096   // B*S
#define NB   2

typedef __half fp16;

// ---------------- scratch (static device globals; no allocation) ----------------
__device__ float g_s1 [MROWS * BDIM];
__device__ float g_x1 [MROWS * BDIM];
__device__ float g_s2 [MROWS * BDIM];

__device__ fp16 g_xh  [MROWS * BDIM];
__device__ fp16 g_yh  [MROWS * BDIM];
__device__ fp16 g_Qhi [MROWS * BDIM];   // [B,H,S,DK]
__device__ fp16 g_Qlo [MROWS * BDIM];
__device__ fp16 g_Kh  [MROWS * BDIM];
__device__ fp16 g_Vh  [MROWS * BDIM];
__device__ fp16 g_ah  [MROWS * BDIM];   // attention output [B,S,D]
__device__ fp16 g_x1h [MROWS * BDIM];
__device__ fp16 g_hh  [MROWS * HIDN];

// transposed + split weights: Wt[N][K] fp16 hi/lo
__device__ fp16 g_wqT_hi[BDIM * BDIM], g_wqT_lo[BDIM * BDIM];
__device__ fp16 g_wkT_hi[BDIM * BDIM], g_wkT_lo[BDIM * BDIM];
__device__ fp16 g_wvT_hi[BDIM * BDIM], g_wvT_lo[BDIM * BDIM];
__device__ fp16 g_woT_hi[BDIM * BDIM], g_woT_lo[BDIM * BDIM];
__device__ fp16 g_w1T_hi[HIDN * BDIM], g_w1T_lo[HIDN * BDIM];
__device__ fp16 g_w2T_hi[BDIM * HIDN], g_w2T_lo[BDIM * HIDN];

enum { MODE_RELU_H = 1, MODE_RES = 2, MODE_SPLIT_HL = 3, MODE_SPLIT_H = 4 };

// ======================= PTX helpers =======================
__device__ __forceinline__ uint32_t smem_u32(const void* p) {
    uint32_t a;
    asm("{ .reg .u64 t; cvta.to.shared.u64 t, %1; cvt.u32.u64 %0, t; }" : "=r"(a) : "l"(p));
    return a;
}
__device__ __forceinline__ void cp16(uint32_t s, const void* g) {
    asm volatile("cp.async.cg.shared.global [%0], [%1], 16;" :: "r"(s), "l"(g));
}
#define CP_COMMIT() asm volatile("cp.async.commit_group;" ::: "memory")
#define CP_WAIT0()  asm volatile("cp.async.wait_group 0;" ::: "memory")
#define CP_WAIT1()  asm volatile("cp.async.wait_group 1;" ::: "memory")

__device__ __forceinline__ void ldm_x4(uint32_t& r0, uint32_t& r1, uint32_t& r2, uint32_t& r3, uint32_t a) {
    asm volatile("ldmatrix.sync.aligned.m8n8.x4.shared.b16 {%0,%1,%2,%3}, [%4];"
                 : "=r"(r0), "=r"(r1), "=r"(r2), "=r"(r3) : "r"(a));
}
__device__ __forceinline__ void ldm_x4_t(uint32_t& r0, uint32_t& r1, uint32_t& r2, uint32_t& r3, uint32_t a) {
    asm volatile("ldmatrix.sync.aligned.m8n8.x4.trans.shared.b16 {%0,%1,%2,%3}, [%4];"
                 : "=r"(r0), "=r"(r1), "=r"(r2), "=r"(r3) : "r"(a));
}
__device__ __forceinline__ void mma16816(float* c, const uint32_t* a, const uint32_t* b) {
    asm volatile("mma.sync.aligned.m16n8k16.row.col.f32.f16.f16.f32 "
                 "{%0,%1,%2,%3}, {%4,%5,%6,%7}, {%8,%9}, {%0,%1,%2,%3};"
                 : "+f"(c[0]), "+f"(c[1]), "+f"(c[2]), "+f"(c[3])
                 : "r"(a[0]), "r"(a[1]), "r"(a[2]), "r"(a[3]), "r"(b[0]), "r"(b[1]));
}
__device__ __forceinline__ uint32_t cvt2(float a, float b) {
    __half2 t = __floats2half2_rn(a, b);
    return *(uint32_t*)&t;
}

// ======================= mma.sync fp16 2-pass GEMM =======================
// C[M,N] = A[M,K] @ (Bhi + Blo)[N,K]^T, fp32 accum. A single fp16.
// CTA 128x128, BK=32, 256 threads = 8 warps (2 M x 4 N).
#define BK 32
#define APAD 40
#define TILE_B (128 * APAD * 2)        // 10240 B
#define SLAB_B (3 * TILE_B)            // A, Bhi, Blo
#define GEMM_SMEM (2 * SLAB_B)         // 61440 B

__global__ __launch_bounds__(256, 2) void mma_gemm(
    const fp16* __restrict__ A,
    const fp16* __restrict__ Bhi, const fp16* __restrict__ Blo,
    const float* __restrict__ bias, const float* __restrict__ R,
    float* __restrict__ outF, fp16* __restrict__ outH, fp16* __restrict__ outL,
    int M, int N, int K, int mode)
{
    extern __shared__ char sm[];
    const uint32_t smb = smem_u32(sm);
    const int tid = threadIdx.x;
    const int wid = tid >> 5;
    const int lid = tid & 31;
    const int warp_m = wid >> 2;
    const int warp_n = wid & 3;
    const int row0 = blockIdx.y * 128;
    const int col0 = blockIdx.x * 128;

    const fp16* src[3];
    src[0] = A   + (size_t)row0 * K;
    src[1] = Bhi + (size_t)col0 * K;
    src[2] = Blo + (size_t)col0 * K;

    const int NS = K / BK;

#define LOAD_SLAB(ST, KS) do {                                                \
        const uint32_t _sb = smb + (ST) * SLAB_B;                             \
        const int _ko = (KS) * BK;                                            \
        _Pragma("unroll")                                                     \
        for (int t = 0; t < 3; t++) {                                         \
            const fp16* g = src[t] + _ko;                                     \
            const uint32_t tb = _sb + t * TILE_B;                             \
            _Pragma("unroll")                                                 \
            for (int u = 0; u < 2; u++) {                                     \
                int p = tid + u * 256;                                        \
                int r = p >> 2, c = p & 3;                                    \
                cp16(tb + (uint32_t)(r * (APAD * 2) + c * 16),                \
                     g + (size_t)r * K + c * 8);                              \
            }                                                                 \
        }                                                                     \
        CP_COMMIT();                                                          \
    } while (0)

    float acc[4][4][4];
#pragma unroll
    for (int i = 0; i < 4; i++)
#pragma unroll
        for (int j = 0; j < 4; j++)
#pragma unroll
            for (int f = 0; f < 4; f++) acc[i][j][f] = 0.f;

    LOAD_SLAB(0, 0);

    const uint32_t lrow = (uint32_t)(lid & 15);
    const uint32_t lcol16 = (uint32_t)(lid >> 4) * 16;

    for (int s = 0; s < NS; s++) {
        const int st = s & 1;
        if (s + 1 < NS) { LOAD_SLAB(st ^ 1, s + 1); CP_WAIT1(); }
        else            { CP_WAIT0(); }
        __syncthreads();

        const uint32_t ab   = smb + st * SLAB_B;
        const uint32_t bb_h = ab + TILE_B;
        const uint32_t bb_l = ab + 2 * TILE_B;

#pragma unroll
        for (int kk = 0; kk < 2; kk++) {
            const uint32_t koff = kk * 32 + lcol16;

            uint32_t af[4][4];
#pragma unroll
            for (int mi = 0; mi < 4; mi++) {
                uint32_t ra = (uint32_t)((warp_m * 64 + mi * 16 + lrow) * (APAD * 2)) + koff;
                ldm_x4(af[mi][0], af[mi][1], af[mi][2], af[mi][3], ab + ra);
            }
            uint32_t bh[4][2], bl[4][2];
#pragma unroll
            for (int nt = 0; nt < 2; nt++) {
                uint32_t rb = (uint32_t)((warp_n * 32 + nt * 16 + lrow) * (APAD * 2)) + koff;
                uint32_t r0, r1, r2, r3;
                ldm_x4(r0, r1, r2, r3, bb_h + rb);
                bh[nt * 2 + 0][0] = r0; bh[nt * 2 + 0][1] = r2;
                bh[nt * 2 + 1][0] = r1; bh[nt * 2 + 1][1] = r3;
                ldm_x4(r0, r1, r2, r3, bb_l + rb);
                bl[nt * 2 + 0][0] = r0; bl[nt * 2 + 0][1] = r2;
                bl[nt * 2 + 1][0] = r1; bl[nt * 2 + 1][1] = r3;
            }
#pragma unroll
            for (int mi = 0; mi < 4; mi++)
#pragma unroll
                for (int ni = 0; ni < 4; ni++) {
                    mma16816(acc[mi][ni], af[mi], bh[ni]);
                    mma16816(acc[mi][ni], af[mi], bl[ni]);
                }
        }
        __syncthreads();
    }

    // ---- epilogue ----
    const int qr = lid >> 2;
    const int qc = (lid & 3) * 2;
#pragma unroll
    for (int mi = 0; mi < 4; mi++) {
#pragma unroll
        for (int ni = 0; ni < 4; ni++) {
            const int n = col0 + warp_n * 32 + ni * 8 + qc;
            const float b0 = bias[n], b1 = bias[n + 1];
#pragma unroll
            for (int half = 0; half < 2; half++) {
                const int m = row0 + warp_m * 64 + mi * 16 + qr + half * 8;
                float v0 = acc[mi][ni][half * 2 + 0] + b0;
                float v1 = acc[mi][ni][half * 2 + 1] + b1;
                if (mode == MODE_RES) {
                    const float* rp = &R[(size_t)m * N + n];
                    v0 += rp[0]; v1 += rp[1];
                    float2 o2 = {v0, v1};
                    *(float2*)&outF[(size_t)m * N + n] = o2;
                } else if (mode == MODE_SPLIT_HL || mode == MODE_SPLIT_H) {
                    int hh = n >> 6, dk = n & 63, bb = m >> 11, ss = m & 2047;
                    size_t o = (((size_t)(bb * NH + hh)) * SEQ + ss) * DKH + dk;
                    fp16 h0 = __float2half(v0), h1 = __float2half(v1);
                    __half2 p; p.x = h0; p.y = h1;
                    *(__half2*)&outH[o] = p;
                    if (mode == MODE_SPLIT_HL) {
                        p.x = __float2half(v0 - __half2float(h0));
                        p.y = __float2half(v1 - __half2float(h1));
                        *(__half2*)&outL[o] = p;
                    }
                } else { // MODE_RELU_H
                    v0 = fmaxf(v0, 0.f); v1 = fmaxf(v1, 0.f);
                    __half2 p = __floats2half2_rn(v0, v1);
                    *(__half2*)&outH[(size_t)m * N + n] = p;
                }
            }
        }
    }
}

// ======================= tensor-core flash attention (fp16) =======================
// Q hi/lo fp16 (register frags), K/V single fp16, all [B,H,S,DK].
// CTA = 128 queries x 1 head, 8 warps x 16 queries, KV tile 64 double-buffered.
#define AT_STRIDE 144
#define AT_TILE   (64 * AT_STRIDE)            // 9216 B per 64x64 fp16 tile
#define AT_STAGE  (2 * AT_TILE)               // K, V
#define AT_MSK    (2 * AT_STAGE)              // 36864
#define AT_SMEM   (AT_MSK + 512)

__global__ __launch_bounds__(256, 1) void attn_tc(
    const fp16* __restrict__ Qhi, const fp16* __restrict__ Qlo,
    const fp16* __restrict__ Kg, const fp16* __restrict__ Vg,
    const int* __restrict__ mask, fp16* __restrict__ O_out)
{
    extern __shared__ char sm[];
    const uint32_t smb = smem_u32(sm);
    const int tid = threadIdx.x;
    const int wid = tid >> 5;
    const int lid = tid & 31;
    const int q0  = blockIdx.x * 128;
    const int h   = blockIdx.y;
    const int bz  = blockIdx.z;
    const size_t hoff = ((size_t)(bz * NH + h)) * SEQ * DKH;

    const uint32_t lr   = (uint32_t)(lid & 15);
    const uint32_t lc16 = (uint32_t)(lid >> 4) * 16;

    // ---- Q tile -> smem (hi @0, lo @18432), then register fragments ----
    {
        const fp16* qh = Qhi + hoff + (size_t)q0 * DKH;
        const fp16* ql = Qlo + hoff + (size_t)q0 * DKH;
#pragma unroll
        for (int u = 0; u < 4; u++) {
            int p = tid + u * 256;
            int r = p >> 3, c = p & 7;
            cp16(smb + (uint32_t)(r * AT_STRIDE + c * 16), qh + (size_t)r * DKH + c * 8);
            cp16(smb + 18432u + (uint32_t)(r * AT_STRIDE + c * 16), ql + (size_t)r * DKH + c * 8);
        }
        CP_COMMIT(); CP_WAIT0();
    }
    __syncthreads();
    uint32_t qfh[4][4], qfl[4][4];
#pragma unroll
    for (int ks = 0; ks < 4; ks++) {
        uint32_t ra = (uint32_t)((wid * 16 + lr) * AT_STRIDE) + ks * 32 + lc16;
        ldm_x4(qfh[ks][0], qfh[ks][1], qfh[ks][2], qfh[ks][3], smb + ra);
        ldm_x4(qfl[ks][0], qfl[ks][1], qfl[ks][2], qfl[ks][3], smb + 18432u + ra);
    }
    __syncthreads();

    float O[8][4];
#pragma unroll
    for (int i = 0; i < 8; i++)
#pragma unroll
        for (int j = 0; j < 4; j++) O[i][j] = 0.f;
    float m0 = -INFINITY, m1 = -INFINITY, l0 = 0.f, l1 = 0.f;

    const fp16* kg = Kg + hoff;
    const fp16* vg = Vg + hoff;
    const int*  mkg = mask + bz * SEQ;

#define LOAD_KV(ST, T) do {                                                     \
        const uint32_t _sb = smb + (ST) * AT_STAGE;                             \
        const int _k0 = (T) * 64;                                               \
        _Pragma("unroll")                                                       \
        for (int u = 0; u < 2; u++) {                                           \
            int p = tid + u * 256;                                              \
            int r = p >> 3, c = p & 7;                                          \
            uint32_t so = (uint32_t)(r * AT_STRIDE + c * 16);                   \
            size_t go = (size_t)(_k0 + r) * DKH + c * 8;                        \
            cp16(_sb + so, kg + go);                                            \
            cp16(_sb + AT_TILE + so, vg + go);                                  \
        }                                                                       \
        if (tid < 16) cp16(smb + AT_MSK + (ST) * 256 + tid * 16, mkg + _k0 + tid * 4); \
        CP_COMMIT();                                                            \
    } while (0)

    LOAD_KV(0, 0);

    for (int t = 0; t < SEQ / 64; t++) {
        const int st = t & 1;
        if (t + 1 < SEQ / 64) { LOAD_KV(st ^ 1, t + 1); CP_WAIT1(); }
        else                  { CP_WAIT0(); }
        __syncthreads();

        const uint32_t sb = smb + st * AT_STAGE;
        const int* msk = (const int*)(sm + AT_MSK + st * 256);

        // ---- scores: 2-pass split QK^T (Q split, K single) ----
        float s[8][4];
#pragma unroll
        for (int i = 0; i < 8; i++)
#pragma unroll
            for (int j = 0; j < 4; j++) s[i][j] = 0.f;

#pragma unroll
        for (int ks = 0; ks < 4; ks++) {
            const uint32_t koff = ks * 32 + lc16;
#pragma unroll
            for (int g = 0; g < 4; g++) {
                uint32_t rb = (uint32_t)((g * 16 + lr) * AT_STRIDE) + koff;
                uint32_t r0, r1, r2, r3;
                ldm_x4(r0, r1, r2, r3, sb + rb);
                uint32_t b0[2] = {r0, r2}, b1[2] = {r1, r3};
                mma16816(s[2 * g],     qfh[ks], b0);
                mma16816(s[2 * g],     qfl[ks], b0);
                mma16816(s[2 * g + 1], qfh[ks], b1);
                mma16816(s[2 * g + 1], qfl[ks], b1);
            }
        }

        // ---- mask + scale ----
#pragma unroll
        for (int j = 0; j < 8; j++) {
            int c0 = j * 8 + (lid & 3) * 2;
            bool z0 = (msk[c0] == 0), z1 = (msk[c0 + 1] == 0);
            s[j][0] = z0 ? -1e9f : s[j][0] * 0.125f;
            s[j][2] = z0 ? -1e9f : s[j][2] * 0.125f;
            s[j][1] = z1 ? -1e9f : s[j][1] * 0.125f;
            s[j][3] = z1 ? -1e9f : s[j][3] * 0.125f;
        }

        // ---- online softmax (rows r and r+8) ----
        float mx0 = -INFINITY, mx1 = -INFINITY;
#pragma unroll
        for (int j = 0; j < 8; j++) {
            mx0 = fmaxf(mx0, fmaxf(s[j][0], s[j][1]));
            mx1 = fmaxf(mx1, fmaxf(s[j][2], s[j][3]));
        }
#pragma unroll
        for (int off = 1; off <= 2; off <<= 1) {
            mx0 = fmaxf(mx0, __shfl_xor_sync(0xffffffffu, mx0, off));
            mx1 = fmaxf(mx1, __shfl_xor_sync(0xffffffffu, mx1, off));
        }
        float nm0 = fmaxf(m0, mx0), nm1 = fmaxf(m1, mx1);
        float a0 = __expf(m0 - nm0), a1 = __expf(m1 - nm1);
        float sum0 = 0.f, sum1 = 0.f;
#pragma unroll
        for (int j = 0; j < 8; j++) {
            s[j][0] = __expf(s[j][0] - nm0); sum0 += s[j][0];
            s[j][1] = __expf(s[j][1] - nm0); sum0 += s[j][1];
            s[j][2] = __expf(s[j][2] - nm1); sum1 += s[j][2];
            s[j][3] = __expf(s[j][3] - nm1); sum1 += s[j][3];
        }
#pragma unroll
        for (int off = 1; off <= 2; off <<= 1) {
            sum0 += __shfl_xor_sync(0xffffffffu, sum0, off);
            sum1 += __shfl_xor_sync(0xffffffffu, sum1, off);
        }
        l0 = l0 * a0 + sum0;
        l1 = l1 * a1 + sum1;
        m0 = nm0; m1 = nm1;
#pragma unroll
        for (int i = 0; i < 8; i++) {
            O[i][0] *= a0; O[i][1] *= a0;
            O[i][2] *= a1; O[i][3] *= a1;
        }

        // ---- O += P @ V (P from registers, V via ldmatrix.trans) ----
#pragma unroll
        for (int j = 0; j < 4; j++) {
            uint32_t P[4];
            P[0] = cvt2(s[2 * j][0],     s[2 * j][1]);
            P[1] = cvt2(s[2 * j][2],     s[2 * j][3]);
            P[2] = cvt2(s[2 * j + 1][0], s[2 * j + 1][1]);
            P[3] = cvt2(s[2 * j + 1][2], s[2 * j + 1][3]);
#pragma unroll
            for (int c = 0; c < 4; c++) {
                uint32_t r0, r1, r2, r3;
                ldm_x4_t(r0, r1, r2, r3,
                         sb + AT_TILE + (uint32_t)((j * 16 + lr) * AT_STRIDE) + c * 32 + lc16);
                uint32_t B0[2] = {r0, r1}, B1[2] = {r2, r3};
                mma16816(O[2 * c],     P, B0);
                mma16816(O[2 * c + 1], P, B1);
            }
        }
        __syncthreads();
    }

    // ---- epilogue: normalize, write single fp16 [B,S,D] ----
    const float il0 = 1.f / (l0 > 0.f ? l0 : 1.f);
    const float il1 = 1.f / (l1 > 0.f ? l1 : 1.f);
    const int qr  = q0 + wid * 16 + (lid >> 2);
    const int col0 = h * DKH + (lid & 3) * 2;
#pragma unroll
    for (int nt = 0; nt < 8; nt++) {
        const int col = col0 + nt * 8;
        {
            __half2 p = __floats2half2_rn(O[nt][0] * il0, O[nt][1] * il0);
            *(__half2*)&O_out[((size_t)bz * SEQ + qr) * BDIM + col] = p;
        }
        {
            __half2 p = __floats2half2_rn(O[nt][2] * il1, O[nt][3] * il1);
            *(__half2*)&O_out[((size_t)bz * SEQ + qr + 8) * BDIM + col] = p;
        }
    }
}

// ======================= weight transpose + hi/lo split (fp16) =======================
__global__ __launch_bounds__(256) void wtrans_kernel(
    const float* __restrict__ W, fp16* __restrict__ hiT, fp16* __restrict__ loT,
    int K, int N)
{
    __shared__ float t[32][33];
    const int n0 = blockIdx.x * 32, k0 = blockIdx.y * 32;
    const int tx = threadIdx.x, ty = threadIdx.y;
#pragma unroll
    for (int j = 0; j < 4; j++)
        t[ty + j * 8][tx] = W[(size_t)(k0 + ty + j * 8) * N + n0 + tx];
    __syncthreads();
#pragma unroll
    for (int j = 0; j < 4; j++) {
        float v = t[tx][ty + j * 8];
        fp16 h = __float2half(v);
        size_t o = (size_t)(n0 + ty + j * 8) * K + k0 + tx;
        hiT[o] = h;
        loT[o] = __float2half(v - __half2float(h));
    }
}

// ======================= fp32 -> fp16 =======================
__global__ __launch_bounds__(256) void cvt_h(
    const float* __restrict__ X, fp16* __restrict__ H)
{
    const int i = (blockIdx.x * 256 + threadIdx.x) * 4;
    const float4 v = *(const float4*)(X + i);
    *(__half2*)(H + i)     = __floats2half2_rn(v.x, v.y);
    *(__half2*)(H + i + 2) = __floats2half2_rn(v.z, v.w);
}

// ======================= LayerNorm (+ optional fp16 output) =======================
__global__ __launch_bounds__(256) void ln_kernel(
    const float* __restrict__ X, const float* __restrict__ g,
    const float* __restrict__ b, float* __restrict__ Y, fp16* __restrict__ Yh)
{
    __shared__ float red[2][8];
    __shared__ float stats[2];
    const int row = blockIdx.x;
    const int tid = threadIdx.x;

    const float4 v = ((const float4*)(X + (size_t)row * BDIM))[tid];
    float s = v.x + v.y + v.z + v.w;
    float q = v.x * v.x + v.y * v.y + v.z * v.z + v.w * v.w;
#pragma unroll
    for (int o = 16; o > 0; o >>= 1) {
        s += __shfl_xor_sync(0xffffffffu, s, o);
        q += __shfl_xor_sync(0xffffffffu, q, o);
    }
    const int lane = tid & 31, w = tid >> 5;
    if (lane == 0) { red[0][w] = s; red[1][w] = q; }
    __syncthreads();
    if (tid < 32) {
        s = (tid < 8) ? red[0][tid] : 0.f;
        q = (tid < 8) ? red[1][tid] : 0.f;
#pragma unroll
        for (int o = 4; o > 0; o >>= 1) {
            s += __shfl_xor_sync(0xffffffffu, s, o);
            q += __shfl_xor_sync(0xffffffffu, q, o);
        }
        if (tid == 0) {
            float mean = s * (1.f / BDIM);
            stats[0] = mean;
            stats[1] = rsqrtf(q * (1.f / BDIM) - mean * mean + 1e-5f);
        }
    }
    __syncthreads();
    const float mean = stats[0], rinv = stats[1];
    const float4 gg = ((const float4*)g)[tid];
    const float4 bb = ((const float4*)b)[tid];
    float4 o4;
    o4.x = (v.x - mean) * rinv * gg.x + bb.x;
    o4.y = (v.y - mean) * rinv * gg.y + bb.y;
    o4.z = (v.z - mean) * rinv * gg.z + bb.z;
    o4.w = (v.w - mean) * rinv * gg.w + bb.w;
    if (Y) ((float4*)(Y + (size_t)row * BDIM))[tid] = o4;
    if (Yh) {
        size_t base = (size_t)row * BDIM + tid * 4;
        *(__half2*)(Yh + base)     = __floats2half2_rn(o4.x, o4.y);
        *(__half2*)(Yh + base + 2) = __floats2half2_rn(o4.z, o4.w);
    }
}

// ======================= launcher =======================
extern "C" void kernel_launch(void* const* d_in, const int* in_sizes, int n_in,
                              void* d_out, int out_size)
{
    const float* x    = (const float*)d_in[0];
    const float* y    = (const float*)d_in[1];
    const int*   mask = (const int*)  d_in[2];
    const float* Wq = (const float*)d_in[3];  const float* bq = (const float*)d_in[4];
    const float* Wk = (const float*)d_in[5];  const float* bk = (const float*)d_in[6];
    const float* Wv = (const float*)d_in[7];  const float* bv = (const float*)d_in[8];
    const float* Wo = (const float*)d_in[9];  const float* bo = (const float*)d_in[10];
    const float* W1 = (const float*)d_in[11]; const float* b1 = (const float*)d_in[12];
    const float* W2 = (const float*)d_in[13]; const float* b2 = (const float*)d_in[14];
    const float* g1 = (const float*)d_in[15]; const float* be1 = (const float*)d_in[16];
    const float* g2 = (const float*)d_in[17]; const float* be2 = (const float*)d_in[18];
    float* out = (float*)d_out;

    float *s1p, *x1p, *s2p;
    fp16 *xh, *yh, *qhi, *qlo, *kh, *vh, *ah, *x1h, *hh;
    fp16 *wq_h, *wq_l, *wk_h, *wk_l, *wv_h, *wv_l, *wo_h, *wo_l, *w1_h, *w1_l, *w2_h, *w2_l;
    cudaGetSymbolAddress((void**)&s1p, g_s1);  cudaGetSymbolAddress((void**)&x1p, g_x1);
    cudaGetSymbolAddress((void**)&s2p, g_s2);
    cudaGetSymbolAddress((void**)&xh, g_xh);   cudaGetSymbolAddress((void**)&yh, g_yh);
    cudaGetSymbolAddress((void**)&qhi, g_Qhi); cudaGetSymbolAddress((void**)&qlo, g_Qlo);
    cudaGetSymbolAddress((void**)&kh, g_Kh);   cudaGetSymbolAddress((void**)&vh, g_Vh);
    cudaGetSymbolAddress((void**)&ah, g_ah);   cudaGetSymbolAddress((void**)&x1h, g_x1h);
    cudaGetSymbolAddress((void**)&hh, g_hh);
    cudaGetSymbolAddress((void**)&wq_h, g_wqT_hi); cudaGetSymbolAddress((void**)&wq_l, g_wqT_lo);
    cudaGetSymbolAddress((void**)&wk_h, g_wkT_hi); cudaGetSymbolAddress((void**)&wk_l, g_wkT_lo);
    cudaGetSymbolAddress((void**)&wv_h, g_wvT_hi); cudaGetSymbolAddress((void**)&wv_l, g_wvT_lo);
    cudaGetSymbolAddress((void**)&wo_h, g_woT_hi); cudaGetSymbolAddress((void**)&wo_l, g_woT_lo);
    cudaGetSymbolAddress((void**)&w1_h, g_w1T_hi); cudaGetSymbolAddress((void**)&w1_l, g_w1T_lo);
    cudaGetSymbolAddress((void**)&w2_h, g_w2T_hi); cudaGetSymbolAddress((void**)&w2_l, g_w2T_lo);

    cudaFuncSetAttribute(mma_gemm, cudaFuncAttributeMaxDynamicSharedMemorySize, GEMM_SMEM);
    cudaFuncSetAttribute(attn_tc,  cudaFuncAttributeMaxDynamicSharedMemorySize, AT_SMEM);

    // ---- weight prep (transpose + fp16 hi/lo split) ----
    dim3 tb(32, 8);
    wtrans_kernel<<<dim3(BDIM / 32, BDIM / 32), tb>>>(Wq, wq_h, wq_l, BDIM, BDIM);
    wtrans_kernel<<<dim3(BDIM / 32, BDIM / 32), tb>>>(Wk, wk_h, wk_l, BDIM, BDIM);
    wtrans_kernel<<<dim3(BDIM / 32, BDIM / 32), tb>>>(Wv, wv_h, wv_l, BDIM, BDIM);
    wtrans_kernel<<<dim3(BDIM / 32, BDIM / 32), tb>>>(Wo, wo_h, wo_l, BDIM, BDIM);
    wtrans_kernel<<<dim3(HIDN / 32, BDIM / 32), tb>>>(W1, w1_h, w1_l, BDIM, HIDN);
    wtrans_kernel<<<dim3(BDIM / 32, HIDN / 32), tb>>>(W2, w2_h, w2_l, HIDN, BDIM);

    // ---- activation fp16 conversion ----
    cvt_h<<<(MROWS * BDIM) / 1024, 256>>>(x, xh);
    cvt_h<<<(MROWS * BDIM) / 1024, 256>>>(y, yh);

    dim3 gD(BDIM / 128, MROWS / 128);
    dim3 gH(HIDN / 128, MROWS / 128);

    // QKV projections -> [B,H,S,DK] fp16 (Q hi/lo, K/V single)
    mma_gemm<<<gD, 256, GEMM_SMEM>>>(xh, wq_h, wq_l, bq, nullptr, nullptr, qhi, qlo, MROWS, BDIM, BDIM, MODE_SPLIT_HL);
    mma_gemm<<<gD, 256, GEMM_SMEM>>>(yh, wk_h, wk_l, bk, nullptr, nullptr, kh, nullptr, MROWS, BDIM, BDIM, MODE_SPLIT_H);
    mma_gemm<<<gD, 256, GEMM_SMEM>>>(yh, wv_h, wv_l, bv, nullptr, nullptr, vh, nullptr, MROWS, BDIM, BDIM, MODE_SPLIT_H);

    // tensor-core flash attention -> fp16 [B,S,D]
    attn_tc<<<dim3(SEQ / 128, NH, NB), 256, AT_SMEM>>>(qhi, qlo, kh, vh, mask, ah);

    // s1 = x + attn @ Wo + bo ; x1 = LN(s1) (+fp16)
    mma_gemm<<<gD, 256, GEMM_SMEM>>>(ah, wo_h, wo_l, bo, x, s1p, nullptr, nullptr, MROWS, BDIM, BDIM, MODE_RES);
    ln_kernel<<<MROWS, 256>>>(s1p, g1, be1, x1p, x1h);

    // FFN
    mma_gemm<<<gH, 256, GEMM_SMEM>>>(x1h, w1_h, w1_l, b1, nullptr, nullptr, hh, nullptr, MROWS, HIDN, BDIM, MODE_RELU_H);
    mma_gemm<<<gD, 256, GEMM_SMEM>>>(hh, w2_h, w2_l, b2, x1p, s2p, nullptr, nullptr, MROWS, BDIM, HIDN, MODE_RES);
    ln_kernel<<<MROWS, 256>>>(s2p, g2, be2, out, nullptr);
}

// round 9
// speedup vs baseline: 5.2803x; 1.4973x over previous
#include <cuda_runtime.h>
#include <cuda_fp16.h>
#include <math.h>
#include <stdint.h>

#define BDIM 1024
#define SEQ  2048
#define NH   16
#define DKH  64
#define HIDN 4096
#define MROWS 4096   // B*S
#define NB   2

typedef __half fp16;

// ---------------- scratch (static device globals; no allocation) ----------------
__device__ float g_s1 [MROWS * BDIM];
__device__ float g_x1 [MROWS * BDIM];
__device__ float g_s2 [MROWS * BDIM];

__device__ fp16 g_xh  [MROWS * BDIM];
__device__ fp16 g_yh  [MROWS * BDIM];
__device__ fp16 g_Qh  [MROWS * BDIM];   // [B,H,S,DK]
__device__ fp16 g_Kh  [MROWS * BDIM];
__device__ fp16 g_Vh  [MROWS * BDIM];
__device__ fp16 g_ah  [MROWS * BDIM];   // attention output [B,S,D]
__device__ fp16 g_x1h [MROWS * BDIM];
__device__ fp16 g_hh  [MROWS * HIDN];

// transposed weights: Wt[N][K] fp16
__device__ fp16 g_wqT[BDIM * BDIM];
__device__ fp16 g_wkT[BDIM * BDIM];
__device__ fp16 g_wvT[BDIM * BDIM];
__device__ fp16 g_woT[BDIM * BDIM];
__device__ fp16 g_w1T[HIDN * BDIM];
__device__ fp16 g_w2T[BDIM * HIDN];

enum { MODE_RELU_H = 1, MODE_RES = 2, MODE_SPLIT_H = 4 };

// ======================= PTX helpers =======================
__device__ __forceinline__ uint32_t smem_u32(const void* p) {
    uint32_t a;
    asm("{ .reg .u64 t; cvta.to.shared.u64 t, %1; cvt.u32.u64 %0, t; }" : "=r"(a) : "l"(p));
    return a;
}
__device__ __forceinline__ void cp16(uint32_t s, const void* g) {
    asm volatile("cp.async.cg.shared.global [%0], [%1], 16;" :: "r"(s), "l"(g));
}
#define CP_COMMIT() asm volatile("cp.async.commit_group;" ::: "memory")
#define CP_WAIT0()  asm volatile("cp.async.wait_group 0;" ::: "memory")
#define CP_WAIT1()  asm volatile("cp.async.wait_group 1;" ::: "memory")

__device__ __forceinline__ void ldm_x4(uint32_t& r0, uint32_t& r1, uint32_t& r2, uint32_t& r3, uint32_t a) {
    asm volatile("ldmatrix.sync.aligned.m8n8.x4.shared.b16 {%0,%1,%2,%3}, [%4];"
                 : "=r"(r0), "=r"(r1), "=r"(r2), "=r"(r3) : "r"(a));
}
__device__ __forceinline__ void ldm_x4_t(uint32_t& r0, uint32_t& r1, uint32_t& r2, uint32_t& r3, uint32_t a) {
    asm volatile("ldmatrix.sync.aligned.m8n8.x4.trans.shared.b16 {%0,%1,%2,%3}, [%4];"
                 : "=r"(r0), "=r"(r1), "=r"(r2), "=r"(r3) : "r"(a));
}
__device__ __forceinline__ void mma16816(float* c, const uint32_t* a, const uint32_t* b) {
    asm volatile("mma.sync.aligned.m16n8k16.row.col.f32.f16.f16.f32 "
                 "{%0,%1,%2,%3}, {%4,%5,%6,%7}, {%8,%9}, {%0,%1,%2,%3};"
                 : "+f"(c[0]), "+f"(c[1]), "+f"(c[2]), "+f"(c[3])
                 : "r"(a[0]), "r"(a[1]), "r"(a[2]), "r"(a[3]), "r"(b[0]), "r"(b[1]));
}
__device__ __forceinline__ uint32_t cvt2(float a, float b) {
    __half2 t = __floats2half2_rn(a, b);
    return *(uint32_t*)&t;
}

// ======================= mma.sync fp16 single-pass GEMM =======================
// C[M,N] = A[M,K] @ Wt[N,K]^T, fp32 accum.
// CTA 128x128, BK=32, 256 threads = 8 warps (2 M x 4 N), warp tile 64x32.
#define BK 32
#define APAD 40
#define TILE_B (128 * APAD * 2)        // 10240 B
#define SLAB_B (2 * TILE_B)            // A, B
#define GEMM_SMEM (2 * SLAB_B)         // 40960 B

__global__ __launch_bounds__(256, 2) void mma_gemm(
    const fp16* __restrict__ A, const fp16* __restrict__ B,
    const float* __restrict__ bias, const float* __restrict__ R,
    float* __restrict__ outF, fp16* __restrict__ outH,
    int M, int N, int K, int mode)
{
    extern __shared__ char sm[];
    const uint32_t smb = smem_u32(sm);
    const int tid = threadIdx.x;
    const int wid = tid >> 5;
    const int lid = tid & 31;
    const int warp_m = wid >> 2;
    const int warp_n = wid & 3;
    const int row0 = blockIdx.y * 128;
    const int col0 = blockIdx.x * 128;

    const fp16* src[2];
    src[0] = A + (size_t)row0 * K;
    src[1] = B + (size_t)col0 * K;

    const int NS = K / BK;

#define LOAD_SLAB(ST, KS) do {                                                \
        const uint32_t _sb = smb + (ST) * SLAB_B;                             \
        const int _ko = (KS) * BK;                                            \
        _Pragma("unroll")                                                     \
        for (int t = 0; t < 2; t++) {                                         \
            const fp16* g = src[t] + _ko;                                     \
            const uint32_t tb = _sb + t * TILE_B;                             \
            _Pragma("unroll")                                                 \
            for (int u = 0; u < 2; u++) {                                     \
                int p = tid + u * 256;                                        \
                int r = p >> 2, c = p & 3;                                    \
                cp16(tb + (uint32_t)(r * (APAD * 2) + c * 16),                \
                     g + (size_t)r * K + c * 8);                              \
            }                                                                 \
        }                                                                     \
        CP_COMMIT();                                                          \
    } while (0)

    float acc[4][4][4];
#pragma unroll
    for (int i = 0; i < 4; i++)
#pragma unroll
        for (int j = 0; j < 4; j++)
#pragma unroll
            for (int f = 0; f < 4; f++) acc[i][j][f] = 0.f;

    LOAD_SLAB(0, 0);

    const uint32_t lrow = (uint32_t)(lid & 15);
    const uint32_t lcol16 = (uint32_t)(lid >> 4) * 16;

    for (int s = 0; s < NS; s++) {
        const int st = s & 1;
        if (s + 1 < NS) { LOAD_SLAB(st ^ 1, s + 1); CP_WAIT1(); }
        else            { CP_WAIT0(); }
        __syncthreads();

        const uint32_t ab = smb + st * SLAB_B;
        const uint32_t bb = ab + TILE_B;

#pragma unroll
        for (int kk = 0; kk < 2; kk++) {
            const uint32_t koff = kk * 32 + lcol16;

            uint32_t af[4][4];
#pragma unroll
            for (int mi = 0; mi < 4; mi++) {
                uint32_t ra = (uint32_t)((warp_m * 64 + mi * 16 + lrow) * (APAD * 2)) + koff;
                ldm_x4(af[mi][0], af[mi][1], af[mi][2], af[mi][3], ab + ra);
            }
            uint32_t bf[4][2];
#pragma unroll
            for (int nt = 0; nt < 2; nt++) {
                uint32_t rb = (uint32_t)((warp_n * 32 + nt * 16 + lrow) * (APAD * 2)) + koff;
                uint32_t r0, r1, r2, r3;
                ldm_x4(r0, r1, r2, r3, bb + rb);
                bf[nt * 2 + 0][0] = r0; bf[nt * 2 + 0][1] = r2;
                bf[nt * 2 + 1][0] = r1; bf[nt * 2 + 1][1] = r3;
            }
#pragma unroll
            for (int mi = 0; mi < 4; mi++)
#pragma unroll
                for (int ni = 0; ni < 4; ni++)
                    mma16816(acc[mi][ni], af[mi], bf[ni]);
        }
        __syncthreads();
    }

    // ---- epilogue ----
    const int qr = lid >> 2;
    const int qc = (lid & 3) * 2;
#pragma unroll
    for (int mi = 0; mi < 4; mi++) {
#pragma unroll
        for (int ni = 0; ni < 4; ni++) {
            const int n = col0 + warp_n * 32 + ni * 8 + qc;
            const float b0 = bias[n], b1 = bias[n + 1];
#pragma unroll
            for (int half = 0; half < 2; half++) {
                const int m = row0 + warp_m * 64 + mi * 16 + qr + half * 8;
                float v0 = acc[mi][ni][half * 2 + 0] + b0;
                float v1 = acc[mi][ni][half * 2 + 1] + b1;
                if (mode == MODE_RES) {
                    const float* rp = &R[(size_t)m * N + n];
                    v0 += rp[0]; v1 += rp[1];
                    float2 o2 = {v0, v1};
                    *(float2*)&outF[(size_t)m * N + n] = o2;
                } else if (mode == MODE_SPLIT_H) {
                    int hh = n >> 6, dk = n & 63, bb = m >> 11, ss = m & 2047;
                    size_t o = (((size_t)(bb * NH + hh)) * SEQ + ss) * DKH + dk;
                    *(__half2*)&outH[o] = __floats2half2_rn(v0, v1);
                } else { // MODE_RELU_H
                    v0 = fmaxf(v0, 0.f); v1 = fmaxf(v1, 0.f);
                    *(__half2*)&outH[(size_t)m * N + n] = __floats2half2_rn(v0, v1);
                }
            }
        }
    }
}

// ======================= tensor-core flash attention (fp16, single-pass) =======================
// Q/K/V single fp16, all [B,H,S,DK]. CTA = 128 queries x 1 head.
// 8 warps x 16 queries, KV tile 64 double-buffered.
#define AT_STRIDE 144
#define AT_TILE   (64 * AT_STRIDE)            // 9216 B per 64x64 fp16 tile
#define AT_STAGE  (2 * AT_TILE)               // K, V
#define AT_MSK    (2 * AT_STAGE)              // 36864
#define AT_SMEM   (AT_MSK + 512)

__global__ __launch_bounds__(256, 1) void attn_tc(
    const fp16* __restrict__ Qg, const fp16* __restrict__ Kg,
    const fp16* __restrict__ Vg, const int* __restrict__ mask,
    fp16* __restrict__ O_out)
{
    extern __shared__ char sm[];
    const uint32_t smb = smem_u32(sm);
    const int tid = threadIdx.x;
    const int wid = tid >> 5;
    const int lid = tid & 31;
    const int q0  = blockIdx.x * 128;
    const int h   = blockIdx.y;
    const int bz  = blockIdx.z;
    const size_t hoff = ((size_t)(bz * NH + h)) * SEQ * DKH;

    const uint32_t lr   = (uint32_t)(lid & 15);
    const uint32_t lc16 = (uint32_t)(lid >> 4) * 16;

    // ---- Q tile -> smem, then register fragments ----
    {
        const fp16* qh = Qg + hoff + (size_t)q0 * DKH;
#pragma unroll
        for (int u = 0; u < 4; u++) {
            int p = tid + u * 256;
            int r = p >> 3, c = p & 7;
            cp16(smb + (uint32_t)(r * AT_STRIDE + c * 16), qh + (size_t)r * DKH + c * 8);
        }
        CP_COMMIT(); CP_WAIT0();
    }
    __syncthreads();
    uint32_t qf[4][4];
#pragma unroll
    for (int ks = 0; ks < 4; ks++) {
        uint32_t ra = (uint32_t)((wid * 16 + lr) * AT_STRIDE) + ks * 32 + lc16;
        ldm_x4(qf[ks][0], qf[ks][1], qf[ks][2], qf[ks][3], smb + ra);
    }
    __syncthreads();

    float O[8][4];
#pragma unroll
    for (int i = 0; i < 8; i++)
#pragma unroll
        for (int j = 0; j < 4; j++) O[i][j] = 0.f;
    float m0 = -INFINITY, m1 = -INFINITY, l0 = 0.f, l1 = 0.f;

    const fp16* kg = Kg + hoff;
    const fp16* vg = Vg + hoff;
    const int*  mkg = mask + bz * SEQ;

#define LOAD_KV(ST, T) do {                                                     \
        const uint32_t _sb = smb + (ST) * AT_STAGE;                             \
        const int _k0 = (T) * 64;                                               \
        _Pragma("unroll")                                                       \
        for (int u = 0; u < 2; u++) {                                           \
            int p = tid + u * 256;                                              \
            int r = p >> 3, c = p & 7;                                          \
            uint32_t so = (uint32_t)(r * AT_STRIDE + c * 16);                   \
            size_t go = (size_t)(_k0 + r) * DKH + c * 8;                        \
            cp16(_sb + so, kg + go);                                            \
            cp16(_sb + AT_TILE + so, vg + go);                                  \
        }                                                                       \
        if (tid < 16) cp16(smb + AT_MSK + (ST) * 256 + tid * 16, mkg + _k0 + tid * 4); \
        CP_COMMIT();                                                            \
    } while (0)

    LOAD_KV(0, 0);

    for (int t = 0; t < SEQ / 64; t++) {
        const int st = t & 1;
        if (t + 1 < SEQ / 64) { LOAD_KV(st ^ 1, t + 1); CP_WAIT1(); }
        else                  { CP_WAIT0(); }
        __syncthreads();

        const uint32_t sb = smb + st * AT_STAGE;
        const int* msk = (const int*)(sm + AT_MSK + st * 256);

        // ---- scores: single-pass QK^T ----
        float s[8][4];
#pragma unroll
        for (int i = 0; i < 8; i++)
#pragma unroll
            for (int j = 0; j < 4; j++) s[i][j] = 0.f;

#pragma unroll
        for (int ks = 0; ks < 4; ks++) {
            const uint32_t koff = ks * 32 + lc16;
#pragma unroll
            for (int g = 0; g < 4; g++) {
                uint32_t rb = (uint32_t)((g * 16 + lr) * AT_STRIDE) + koff;
                uint32_t r0, r1, r2, r3;
                ldm_x4(r0, r1, r2, r3, sb + rb);
                uint32_t b0[2] = {r0, r2}, b1[2] = {r1, r3};
                mma16816(s[2 * g],     qf[ks], b0);
                mma16816(s[2 * g + 1], qf[ks], b1);
            }
        }

        // ---- mask + scale ----
#pragma unroll
        for (int j = 0; j < 8; j++) {
            int c0 = j * 8 + (lid & 3) * 2;
            bool z0 = (msk[c0] == 0), z1 = (msk[c0 + 1] == 0);
            s[j][0] = z0 ? -1e9f : s[j][0] * 0.125f;
            s[j][2] = z0 ? -1e9f : s[j][2] * 0.125f;
            s[j][1] = z1 ? -1e9f : s[j][1] * 0.125f;
            s[j][3] = z1 ? -1e9f : s[j][3] * 0.125f;
        }

        // ---- online softmax (rows r and r+8) ----
        float mx0 = -INFINITY, mx1 = -INFINITY;
#pragma unroll
        for (int j = 0; j < 8; j++) {
            mx0 = fmaxf(mx0, fmaxf(s[j][0], s[j][1]));
            mx1 = fmaxf(mx1, fmaxf(s[j][2], s[j][3]));
        }
#pragma unroll
        for (int off = 1; off <= 2; off <<= 1) {
            mx0 = fmaxf(mx0, __shfl_xor_sync(0xffffffffu, mx0, off));
            mx1 = fmaxf(mx1, __shfl_xor_sync(0xffffffffu, mx1, off));
        }
        float nm0 = fmaxf(m0, mx0), nm1 = fmaxf(m1, mx1);
        float a0 = __expf(m0 - nm0), a1 = __expf(m1 - nm1);
        float sum0 = 0.f, sum1 = 0.f;
#pragma unroll
        for (int j = 0; j < 8; j++) {
            s[j][0] = __expf(s[j][0] - nm0); sum0 += s[j][0];
            s[j][1] = __expf(s[j][1] - nm0); sum0 += s[j][1];
            s[j][2] = __expf(s[j][2] - nm1); sum1 += s[j][2];
            s[j][3] = __expf(s[j][3] - nm1); sum1 += s[j][3];
        }
#pragma unroll
        for (int off = 1; off <= 2; off <<= 1) {
            sum0 += __shfl_xor_sync(0xffffffffu, sum0, off);
            sum1 += __shfl_xor_sync(0xffffffffu, sum1, off);
        }
        l0 = l0 * a0 + sum0;
        l1 = l1 * a1 + sum1;
        m0 = nm0; m1 = nm1;
#pragma unroll
        for (int i = 0; i < 8; i++) {
            O[i][0] *= a0; O[i][1] *= a0;
            O[i][2] *= a1; O[i][3] *= a1;
        }

        // ---- O += P @ V (P from registers, V via ldmatrix.trans) ----
#pragma unroll
        for (int j = 0; j < 4; j++) {
            uint32_t P[4];
            P[0] = cvt2(s[2 * j][0],     s[2 * j][1]);
            P[1] = cvt2(s[2 * j][2],     s[2 * j][3]);
            P[2] = cvt2(s[2 * j + 1][0], s[2 * j + 1][1]);
            P[3] = cvt2(s[2 * j + 1][2], s[2 * j + 1][3]);
#pragma unroll
            for (int c = 0; c < 4; c++) {
                uint32_t r0, r1, r2, r3;
                ldm_x4_t(r0, r1, r2, r3,
                         sb + AT_TILE + (uint32_t)((j * 16 + lr) * AT_STRIDE) + c * 32 + lc16);
                uint32_t B0[2] = {r0, r1}, B1[2] = {r2, r3};
                mma16816(O[2 * c],     P, B0);
                mma16816(O[2 * c + 1], P, B1);
            }
        }
        __syncthreads();
    }

    // ---- epilogue: normalize, write fp16 [B,S,D] ----
    const float il0 = 1.f / (l0 > 0.f ? l0 : 1.f);
    const float il1 = 1.f / (l1 > 0.f ? l1 : 1.f);
    const int qr  = q0 + wid * 16 + (lid >> 2);
    const int col0 = h * DKH + (lid & 3) * 2;
#pragma unroll
    for (int nt = 0; nt < 8; nt++) {
        const int col = col0 + nt * 8;
        {
            __half2 p = __floats2half2_rn(O[nt][0] * il0, O[nt][1] * il0);
            *(__half2*)&O_out[((size_t)bz * SEQ + qr) * BDIM + col] = p;
        }
        {
            __half2 p = __floats2half2_rn(O[nt][2] * il1, O[nt][3] * il1);
            *(__half2*)&O_out[((size_t)bz * SEQ + qr + 8) * BDIM + col] = p;
        }
    }
}

// ======================= weight transpose (fp32 -> fp16 [N,K]) =======================
__global__ __launch_bounds__(256) void wtrans_kernel(
    const float* __restrict__ W, fp16* __restrict__ T16, int K, int N)
{
    __shared__ float t[32][33];
    const int n0 = blockIdx.x * 32, k0 = blockIdx.y * 32;
    const int tx = threadIdx.x, ty = threadIdx.y;
#pragma unroll
    for (int j = 0; j < 4; j++)
        t[ty + j * 8][tx] = W[(size_t)(k0 + ty + j * 8) * N + n0 + tx];
    __syncthreads();
#pragma unroll
    for (int j = 0; j < 4; j++)
        T16[(size_t)(n0 + ty + j * 8) * K + k0 + tx] = __float2half(t[tx][ty + j * 8]);
}

// ======================= fp32 -> fp16 =======================
__global__ __launch_bounds__(256) void cvt_h(
    const float* __restrict__ X, fp16* __restrict__ H)
{
    const int i = (blockIdx.x * 256 + threadIdx.x) * 4;
    const float4 v = *(const float4*)(X + i);
    *(__half2*)(H + i)     = __floats2half2_rn(v.x, v.y);
    *(__half2*)(H + i + 2) = __floats2half2_rn(v.z, v.w);
}

// ======================= LayerNorm (+ optional fp16 output) =======================
__global__ __launch_bounds__(256) void ln_kernel(
    const float* __restrict__ X, const float* __restrict__ g,
    const float* __restrict__ b, float* __restrict__ Y, fp16* __restrict__ Yh)
{
    __shared__ float red[2][8];
    __shared__ float stats[2];
    const int row = blockIdx.x;
    const int tid = threadIdx.x;

    const float4 v = ((const float4*)(X + (size_t)row * BDIM))[tid];
    float s = v.x + v.y + v.z + v.w;
    float q = v.x * v.x + v.y * v.y + v.z * v.z + v.w * v.w;
#pragma unroll
    for (int o = 16; o > 0; o >>= 1) {
        s += __shfl_xor_sync(0xffffffffu, s, o);
        q += __shfl_xor_sync(0xffffffffu, q, o);
    }
    const int lane = tid & 31, w = tid >> 5;
    if (lane == 0) { red[0][w] = s; red[1][w] = q; }
    __syncthreads();
    if (tid < 32) {
        s = (tid < 8) ? red[0][tid] : 0.f;
        q = (tid < 8) ? red[1][tid] : 0.f;
#pragma unroll
        for (int o = 4; o > 0; o >>= 1) {
            s += __shfl_xor_sync(0xffffffffu, s, o);
            q += __shfl_xor_sync(0xffffffffu, q, o);
        }
        if (tid == 0) {
            float mean = s * (1.f / BDIM);
            stats[0] = mean;
            stats[1] = rsqrtf(q * (1.f / BDIM) - mean * mean + 1e-5f);
        }
    }
    __syncthreads();
    const float mean = stats[0], rinv = stats[1];
    const float4 gg = ((const float4*)g)[tid];
    const float4 bb = ((const float4*)b)[tid];
    float4 o4;
    o4.x = (v.x - mean) * rinv * gg.x + bb.x;
    o4.y = (v.y - mean) * rinv * gg.y + bb.y;
    o4.z = (v.z - mean) * rinv * gg.z + bb.z;
    o4.w = (v.w - mean) * rinv * gg.w + bb.w;
    if (Y) ((float4*)(Y + (size_t)row * BDIM))[tid] = o4;
    if (Yh) {
        size_t base = (size_t)row * BDIM + tid * 4;
        *(__half2*)(Yh + base)     = __floats2half2_rn(o4.x, o4.y);
        *(__half2*)(Yh + base + 2) = __floats2half2_rn(o4.z, o4.w);
    }
}

// ======================= launcher =======================
extern "C" void kernel_launch(void* const* d_in, const int* in_sizes, int n_in,
                              void* d_out, int out_size)
{
    const float* x    = (const float*)d_in[0];
    const float* y    = (const float*)d_in[1];
    const int*   mask = (const int*)  d_in[2];
    const float* Wq = (const float*)d_in[3];  const float* bq = (const float*)d_in[4];
    const float* Wk = (const float*)d_in[5];  const float* bk = (const float*)d_in[6];
    const float* Wv = (const float*)d_in[7];  const float* bv = (const float*)d_in[8];
    const float* Wo = (const float*)d_in[9];  const float* bo = (const float*)d_in[10];
    const float* W1 = (const float*)d_in[11]; const float* b1 = (const float*)d_in[12];
    const float* W2 = (const float*)d_in[13]; const float* b2 = (const float*)d_in[14];
    const float* g1 = (const float*)d_in[15]; const float* be1 = (const float*)d_in[16];
    const float* g2 = (const float*)d_in[17]; const float* be2 = (const float*)d_in[18];
    float* out = (float*)d_out;

    float *s1p, *x1p, *s2p;
    fp16 *xh, *yh, *qh, *kh, *vh, *ah, *x1h, *hh;
    fp16 *wq, *wk, *wv, *wo, *w1, *w2;
    cudaGetSymbolAddress((void**)&s1p, g_s1);  cudaGetSymbolAddress((void**)&x1p, g_x1);
    cudaGetSymbolAddress((void**)&s2p, g_s2);
    cudaGetSymbolAddress((void**)&xh, g_xh);   cudaGetSymbolAddress((void**)&yh, g_yh);
    cudaGetSymbolAddress((void**)&qh, g_Qh);   cudaGetSymbolAddress((void**)&kh, g_Kh);
    cudaGetSymbolAddress((void**)&vh, g_Vh);   cudaGetSymbolAddress((void**)&ah, g_ah);
    cudaGetSymbolAddress((void**)&x1h, g_x1h); cudaGetSymbolAddress((void**)&hh, g_hh);
    cudaGetSymbolAddress((void**)&wq, g_wqT);  cudaGetSymbolAddress((void**)&wk, g_wkT);
    cudaGetSymbolAddress((void**)&wv, g_wvT);  cudaGetSymbolAddress((void**)&wo, g_woT);
    cudaGetSymbolAddress((void**)&w1, g_w1T);  cudaGetSymbolAddress((void**)&w2, g_w2T);

    cudaFuncSetAttribute(mma_gemm, cudaFuncAttributeMaxDynamicSharedMemorySize, GEMM_SMEM);
    cudaFuncSetAttribute(attn_tc,  cudaFuncAttributeMaxDynamicSharedMemorySize, AT_SMEM);

    // ---- weight prep (transpose to [N,K] fp16) ----
    dim3 tb(32, 8);
    wtrans_kernel<<<dim3(BDIM / 32, BDIM / 32), tb>>>(Wq, wq, BDIM, BDIM);
    wtrans_kernel<<<dim3(BDIM / 32, BDIM / 32), tb>>>(Wk, wk, BDIM, BDIM);
    wtrans_kernel<<<dim3(BDIM / 32, BDIM / 32), tb>>>(Wv, wv, BDIM, BDIM);
    wtrans_kernel<<<dim3(BDIM / 32, BDIM / 32), tb>>>(Wo, wo, BDIM, BDIM);
    wtrans_kernel<<<dim3(HIDN / 32, BDIM / 32), tb>>>(W1, w1, BDIM, HIDN);
    wtrans_kernel<<<dim3(BDIM / 32, HIDN / 32), tb>>>(W2, w2, HIDN, BDIM);

    // ---- activation fp16 conversion ----
    cvt_h<<<(MROWS * BDIM) / 1024, 256>>>(x, xh);
    cvt_h<<<(MROWS * BDIM) / 1024, 256>>>(y, yh);

    dim3 gD(BDIM / 128, MROWS / 128);
    dim3 gH(HIDN / 128, MROWS / 128);

    // QKV projections -> [B,H,S,DK] fp16
    mma_gemm<<<gD, 256, GEMM_SMEM>>>(xh, wq, bq, nullptr, nullptr, qh, MROWS, BDIM, BDIM, MODE_SPLIT_H);
    mma_gemm<<<gD, 256, GEMM_SMEM>>>(yh, wk, bk, nullptr, nullptr, kh, MROWS, BDIM, BDIM, MODE_SPLIT_H);
    mma_gemm<<<gD, 256, GEMM_SMEM>>>(yh, wv, bv, nullptr, nullptr, vh, MROWS, BDIM, BDIM, MODE_SPLIT_H);

    // tensor-core flash attention -> fp16 [B,S,D]
    attn_tc<<<dim3(SEQ / 128, NH, NB), 256, AT_SMEM>>>(qh, kh, vh, mask, ah);

    // s1 = x + attn @ Wo + bo ; x1 = LN(s1) (+fp16)
    mma_gemm<<<gD, 256, GEMM_SMEM>>>(ah, wo, bo, x, s1p, nullptr, MROWS, BDIM, BDIM, MODE_RES);
    ln_kernel<<<MROWS, 256>>>(s1p, g1, be1, x1p, x1h);

    // FFN
    mma_gemm<<<gH, 256, GEMM_SMEM>>>(x1h, w1, b1, nullptr, nullptr, hh, MROWS, HIDN, BDIM, MODE_RELU_H);
    mma_gemm<<<gD, 256, GEMM_SMEM>>>(hh, w2, b2, x1p, s2p, nullptr, MROWS, BDIM, HIDN, MODE_RES);
    ln_kernel<<<MROWS, 256>>>(s2p, g2, be2, out, nullptr);
}

// round 10
// speedup vs baseline: 5.4698x; 1.0359x over previous
#include <cuda_runtime.h>
#include <cuda_fp16.h>
#include <math.h>
#include <stdint.h>

#define BDIM 1024
#define SEQ  2048
#define NH   16
#define DKH  64
#define HIDN 4096
#define MROWS 4096   // B*S
#define NB   2

typedef __half fp16;

// ---------------- scratch (static device globals; no allocation) ----------------
__device__ float g_s1 [MROWS * BDIM];
__device__ float g_x1 [MROWS * BDIM];
__device__ float g_s2 [MROWS * BDIM];

__device__ fp16 g_xh  [MROWS * BDIM];
__device__ fp16 g_yh  [MROWS * BDIM];
__device__ fp16 g_Qh  [MROWS * BDIM];   // [B,H,S,DK]
__device__ fp16 g_Kh  [MROWS * BDIM];
__device__ fp16 g_Vh  [MROWS * BDIM];
__device__ fp16 g_ah  [MROWS * BDIM];   // attention output [B,S,D]
__device__ fp16 g_x1h [MROWS * BDIM];
__device__ fp16 g_hh  [MROWS * HIDN];

// transposed weights: Wt[N][K] fp16
__device__ fp16 g_wqT[BDIM * BDIM];
__device__ fp16 g_wkT[BDIM * BDIM];
__device__ fp16 g_wvT[BDIM * BDIM];
__device__ fp16 g_woT[BDIM * BDIM];
__device__ fp16 g_w1T[HIDN * BDIM];
__device__ fp16 g_w2T[BDIM * HIDN];

enum { MODE_RELU_H = 1, MODE_RES = 2, MODE_SPLIT_H = 4 };

// ======================= PTX helpers =======================
__device__ __forceinline__ uint32_t smem_u32(const void* p) {
    uint32_t a;
    asm("{ .reg .u64 t; cvta.to.shared.u64 t, %1; cvt.u32.u64 %0, t; }" : "=r"(a) : "l"(p));
    return a;
}
__device__ __forceinline__ void cp16(uint32_t s, const void* g) {
    asm volatile("cp.async.cg.shared.global [%0], [%1], 16;" :: "r"(s), "l"(g));
}
#define CP_COMMIT() asm volatile("cp.async.commit_group;" ::: "memory")
#define CP_WAIT0()  asm volatile("cp.async.wait_group 0;" ::: "memory")
#define CP_WAIT1()  asm volatile("cp.async.wait_group 1;" ::: "memory")
#define CP_WAIT2()  asm volatile("cp.async.wait_group 2;" ::: "memory")

__device__ __forceinline__ void ldm_x4(uint32_t& r0, uint32_t& r1, uint32_t& r2, uint32_t& r3, uint32_t a) {
    asm volatile("ldmatrix.sync.aligned.m8n8.x4.shared.b16 {%0,%1,%2,%3}, [%4];"
                 : "=r"(r0), "=r"(r1), "=r"(r2), "=r"(r3) : "r"(a));
}
__device__ __forceinline__ void ldm_x4_t(uint32_t& r0, uint32_t& r1, uint32_t& r2, uint32_t& r3, uint32_t a) {
    asm volatile("ldmatrix.sync.aligned.m8n8.x4.trans.shared.b16 {%0,%1,%2,%3}, [%4];"
                 : "=r"(r0), "=r"(r1), "=r"(r2), "=r"(r3) : "r"(a));
}
__device__ __forceinline__ void mma16816(float* c, const uint32_t* a, const uint32_t* b) {
    asm volatile("mma.sync.aligned.m16n8k16.row.col.f32.f16.f16.f32 "
                 "{%0,%1,%2,%3}, {%4,%5,%6,%7}, {%8,%9}, {%0,%1,%2,%3};"
                 : "+f"(c[0]), "+f"(c[1]), "+f"(c[2]), "+f"(c[3])
                 : "r"(a[0]), "r"(a[1]), "r"(a[2]), "r"(a[3]), "r"(b[0]), "r"(b[1]));
}
__device__ __forceinline__ uint32_t cvt2(float a, float b) {
    __half2 t = __floats2half2_rn(a, b);
    return *(uint32_t*)&t;
}

// ======================= mma.sync fp16 single-pass GEMM (3-stage pipeline) =======================
// C[M,N] = A[M,K] @ Wt[N,K]^T, fp32 accum.
// CTA 128x128, BK=32, 256 threads = 8 warps (2 M x 4 N), warp tile 64x32.
#define BK 32
#define APAD 40
#define TILE_B (128 * APAD * 2)        // 10240 B
#define SLAB_B (2 * TILE_B)            // A, B
#define GEMM_SMEM (3 * SLAB_B)         // 61440 B (3 stages)

__global__ __launch_bounds__(256, 2) void mma_gemm(
    const fp16* __restrict__ A, const fp16* __restrict__ B,
    const float* __restrict__ bias, const float* __restrict__ R,
    float* __restrict__ outF, fp16* __restrict__ outH,
    int M, int N, int K, int mode)
{
    extern __shared__ char sm[];
    const uint32_t smb = smem_u32(sm);
    const int tid = threadIdx.x;
    const int wid = tid >> 5;
    const int lid = tid & 31;
    const int warp_m = wid >> 2;
    const int warp_n = wid & 3;
    const int row0 = blockIdx.y * 128;
    const int col0 = blockIdx.x * 128;

    const fp16* src[2];
    src[0] = A + (size_t)row0 * K;
    src[1] = B + (size_t)col0 * K;

    const int NS = K / BK;

#define LOAD_SLAB(ST, KS) do {                                                \
        const uint32_t _sb = smb + (ST) * SLAB_B;                             \
        const int _ko = (KS) * BK;                                            \
        _Pragma("unroll")                                                     \
        for (int t = 0; t < 2; t++) {                                         \
            const fp16* g = src[t] + _ko;                                     \
            const uint32_t tb = _sb + t * TILE_B;                             \
            _Pragma("unroll")                                                 \
            for (int u = 0; u < 2; u++) {                                     \
                int p = tid + u * 256;                                        \
                int r = p >> 2, c = p & 3;                                    \
                cp16(tb + (uint32_t)(r * (APAD * 2) + c * 16),                \
                     g + (size_t)r * K + c * 8);                              \
            }                                                                 \
        }                                                                     \
        CP_COMMIT();                                                          \
    } while (0)

    float acc[4][4][4];
#pragma unroll
    for (int i = 0; i < 4; i++)
#pragma unroll
        for (int j = 0; j < 4; j++)
#pragma unroll
            for (int f = 0; f < 4; f++) acc[i][j][f] = 0.f;

    LOAD_SLAB(0, 0);
    LOAD_SLAB(1, 1);   // K >= 1024 always => NS >= 32

    const uint32_t lrow = (uint32_t)(lid & 15);
    const uint32_t lcol16 = (uint32_t)(lid >> 4) * 16;

    int st = 0;
    for (int s = 0; s < NS; s++) {
        if (s + 2 < NS) { LOAD_SLAB((st + 2) % 3, s + 2); CP_WAIT2(); }
        else if (s + 1 < NS) { CP_WAIT1(); }
        else { CP_WAIT0(); }
        __syncthreads();

        const uint32_t ab = smb + st * SLAB_B;
        const uint32_t bb = ab + TILE_B;

#pragma unroll
        for (int kk = 0; kk < 2; kk++) {
            const uint32_t koff = kk * 32 + lcol16;

            uint32_t af[4][4];
#pragma unroll
            for (int mi = 0; mi < 4; mi++) {
                uint32_t ra = (uint32_t)((warp_m * 64 + mi * 16 + lrow) * (APAD * 2)) + koff;
                ldm_x4(af[mi][0], af[mi][1], af[mi][2], af[mi][3], ab + ra);
            }
            uint32_t bf[4][2];
#pragma unroll
            for (int nt = 0; nt < 2; nt++) {
                uint32_t rb = (uint32_t)((warp_n * 32 + nt * 16 + lrow) * (APAD * 2)) + koff;
                uint32_t r0, r1, r2, r3;
                ldm_x4(r0, r1, r2, r3, bb + rb);
                bf[nt * 2 + 0][0] = r0; bf[nt * 2 + 0][1] = r2;
                bf[nt * 2 + 1][0] = r1; bf[nt * 2 + 1][1] = r3;
            }
#pragma unroll
            for (int mi = 0; mi < 4; mi++)
#pragma unroll
                for (int ni = 0; ni < 4; ni++)
                    mma16816(acc[mi][ni], af[mi], bf[ni]);
        }
        __syncthreads();
        st = (st + 1) % 3;
    }

    // ---- epilogue ----
    const int qr = lid >> 2;
    const int qc = (lid & 3) * 2;
#pragma unroll
    for (int mi = 0; mi < 4; mi++) {
#pragma unroll
        for (int ni = 0; ni < 4; ni++) {
            const int n = col0 + warp_n * 32 + ni * 8 + qc;
            const float b0 = bias[n], b1 = bias[n + 1];
#pragma unroll
            for (int half = 0; half < 2; half++) {
                const int m = row0 + warp_m * 64 + mi * 16 + qr + half * 8;
                float v0 = acc[mi][ni][half * 2 + 0] + b0;
                float v1 = acc[mi][ni][half * 2 + 1] + b1;
                if (mode == MODE_RES) {
                    const float* rp = &R[(size_t)m * N + n];
                    v0 += rp[0]; v1 += rp[1];
                    float2 o2 = {v0, v1};
                    *(float2*)&outF[(size_t)m * N + n] = o2;
                } else if (mode == MODE_SPLIT_H) {
                    int hh = n >> 6, dk = n & 63, bb = m >> 11, ss = m & 2047;
                    size_t o = (((size_t)(bb * NH + hh)) * SEQ + ss) * DKH + dk;
                    *(__half2*)&outH[o] = __floats2half2_rn(v0, v1);
                } else { // MODE_RELU_H
                    v0 = fmaxf(v0, 0.f); v1 = fmaxf(v1, 0.f);
                    *(__half2*)&outH[(size_t)m * N + n] = __floats2half2_rn(v0, v1);
                }
            }
        }
    }
}

// ======================= tensor-core flash attention (fp16, single-pass) =======================
// Q/K/V single fp16, all [B,H,S,DK]. CTA = 128 queries x 1 head.
// 8 warps x 16 queries, KV tile 64 double-buffered. 2 CTAs/SM.
#define AT_STRIDE 144
#define AT_TILE   (64 * AT_STRIDE)            // 9216 B per 64x64 fp16 tile
#define AT_STAGE  (2 * AT_TILE)               // K, V
#define AT_MSK    (2 * AT_STAGE)              // 36864
#define AT_SMEM   (AT_MSK + 512)

__global__ __launch_bounds__(256, 2) void attn_tc(
    const fp16* __restrict__ Qg, const fp16* __restrict__ Kg,
    const fp16* __restrict__ Vg, const int* __restrict__ mask,
    fp16* __restrict__ O_out)
{
    extern __shared__ char sm[];
    const uint32_t smb = smem_u32(sm);
    const int tid = threadIdx.x;
    const int wid = tid >> 5;
    const int lid = tid & 31;
    const int q0  = blockIdx.x * 128;
    const int h   = blockIdx.y;
    const int bz  = blockIdx.z;
    const size_t hoff = ((size_t)(bz * NH + h)) * SEQ * DKH;

    const uint32_t lr   = (uint32_t)(lid & 15);
    const uint32_t lc16 = (uint32_t)(lid >> 4) * 16;

    // ---- Q tile -> smem, then register fragments ----
    {
        const fp16* qh = Qg + hoff + (size_t)q0 * DKH;
#pragma unroll
        for (int u = 0; u < 4; u++) {
            int p = tid + u * 256;
            int r = p >> 3, c = p & 7;
            cp16(smb + (uint32_t)(r * AT_STRIDE + c * 16), qh + (size_t)r * DKH + c * 8);
        }
        CP_COMMIT(); CP_WAIT0();
    }
    __syncthreads();
    uint32_t qf[4][4];
#pragma unroll
    for (int ks = 0; ks < 4; ks++) {
        uint32_t ra = (uint32_t)((wid * 16 + lr) * AT_STRIDE) + ks * 32 + lc16;
        ldm_x4(qf[ks][0], qf[ks][1], qf[ks][2], qf[ks][3], smb + ra);
    }
    __syncthreads();

    float O[8][4];
#pragma unroll
    for (int i = 0; i < 8; i++)
#pragma unroll
        for (int j = 0; j < 4; j++) O[i][j] = 0.f;
    float m0 = -INFINITY, m1 = -INFINITY, l0 = 0.f, l1 = 0.f;

    const fp16* kg = Kg + hoff;
    const fp16* vg = Vg + hoff;
    const int*  mkg = mask + bz * SEQ;

#define LOAD_KV(ST, T) do {                                                     \
        const uint32_t _sb = smb + (ST) * AT_STAGE;                             \
        const int _k0 = (T) * 64;                                               \
        _Pragma("unroll")                                                       \
        for (int u = 0; u < 2; u++) {                                           \
            int p = tid + u * 256;                                              \
            int r = p >> 3, c = p & 7;                                          \
            uint32_t so = (uint32_t)(r * AT_STRIDE + c * 16);                   \
            size_t go = (size_t)(_k0 + r) * DKH + c * 8;                        \
            cp16(_sb + so, kg + go);                                            \
            cp16(_sb + AT_TILE + so, vg + go);                                  \
        }                                                                       \
        if (tid < 16) cp16(smb + AT_MSK + (ST) * 256 + tid * 16, mkg + _k0 + tid * 4); \
        CP_COMMIT();                                                            \
    } while (0)

    LOAD_KV(0, 0);

    for (int t = 0; t < SEQ / 64; t++) {
        const int st = t & 1;
        if (t + 1 < SEQ / 64) { LOAD_KV(st ^ 1, t + 1); CP_WAIT1(); }
        else                  { CP_WAIT0(); }
        __syncthreads();

        const uint32_t sb = smb + st * AT_STAGE;
        const int* msk = (const int*)(sm + AT_MSK + st * 256);

        // ---- scores: single-pass QK^T ----
        float s[8][4];
#pragma unroll
        for (int i = 0; i < 8; i++)
#pragma unroll
            for (int j = 0; j < 4; j++) s[i][j] = 0.f;

#pragma unroll
        for (int ks = 0; ks < 4; ks++) {
            const uint32_t koff = ks * 32 + lc16;
#pragma unroll
            for (int g = 0; g < 4; g++) {
                uint32_t rb = (uint32_t)((g * 16 + lr) * AT_STRIDE) + koff;
                uint32_t r0, r1, r2, r3;
                ldm_x4(r0, r1, r2, r3, sb + rb);
                uint32_t b0[2] = {r0, r2}, b1[2] = {r1, r3};
                mma16816(s[2 * g],     qf[ks], b0);
                mma16816(s[2 * g + 1], qf[ks], b1);
            }
        }

        // ---- mask + scale ----
#pragma unroll
        for (int j = 0; j < 8; j++) {
            int c0 = j * 8 + (lid & 3) * 2;
            bool z0 = (msk[c0] == 0), z1 = (msk[c0 + 1] == 0);
            s[j][0] = z0 ? -1e9f : s[j][0] * 0.125f;
            s[j][2] = z0 ? -1e9f : s[j][2] * 0.125f;
            s[j][1] = z1 ? -1e9f : s[j][1] * 0.125f;
            s[j][3] = z1 ? -1e9f : s[j][3] * 0.125f;
        }

        // ---- online softmax (rows r and r+8) ----
        float mx0 = -INFINITY, mx1 = -INFINITY;
#pragma unroll
        for (int j = 0; j < 8; j++) {
            mx0 = fmaxf(mx0, fmaxf(s[j][0], s[j][1]));
            mx1 = fmaxf(mx1, fmaxf(s[j][2], s[j][3]));
        }
#pragma unroll
        for (int off = 1; off <= 2; off <<= 1) {
            mx0 = fmaxf(mx0, __shfl_xor_sync(0xffffffffu, mx0, off));
            mx1 = fmaxf(mx1, __shfl_xor_sync(0xffffffffu, mx1, off));
        }
        float nm0 = fmaxf(m0, mx0), nm1 = fmaxf(m1, mx1);
        float a0 = __expf(m0 - nm0), a1 = __expf(m1 - nm1);
        float sum0 = 0.f, sum1 = 0.f;
#pragma unroll
        for (int j = 0; j < 8; j++) {
            s[j][0] = __expf(s[j][0] - nm0); sum0 += s[j][0];
            s[j][1] = __expf(s[j][1] - nm0); sum0 += s[j][1];
            s[j][2] = __expf(s[j][2] - nm1); sum1 += s[j][2];
            s[j][3] = __expf(s[j][3] - nm1); sum1 += s[j][3];
        }
#pragma unroll
        for (int off = 1; off <= 2; off <<= 1) {
            sum0 += __shfl_xor_sync(0xffffffffu, sum0, off);
            sum1 += __shfl_xor_sync(0xffffffffu, sum1, off);
        }
        l0 = l0 * a0 + sum0;
        l1 = l1 * a1 + sum1;
        m0 = nm0; m1 = nm1;
#pragma unroll
        for (int i = 0; i < 8; i++) {
            O[i][0] *= a0; O[i][1] *= a0;
            O[i][2] *= a1; O[i][3] *= a1;
        }

        // ---- O += P @ V (P from registers, V via ldmatrix.trans) ----
#pragma unroll
        for (int j = 0; j < 4; j++) {
            uint32_t P[4];
            P[0] = cvt2(s[2 * j][0],     s[2 * j][1]);
            P[1] = cvt2(s[2 * j][2],     s[2 * j][3]);
            P[2] = cvt2(s[2 * j + 1][0], s[2 * j + 1][1]);
            P[3] = cvt2(s[2 * j + 1][2], s[2 * j + 1][3]);
#pragma unroll
            for (int c = 0; c < 4; c++) {
                uint32_t r0, r1, r2, r3;
                ldm_x4_t(r0, r1, r2, r3,
                         sb + AT_TILE + (uint32_t)((j * 16 + lr) * AT_STRIDE) + c * 32 + lc16);
                uint32_t B0[2] = {r0, r1}, B1[2] = {r2, r3};
                mma16816(O[2 * c],     P, B0);
                mma16816(O[2 * c + 1], P, B1);
            }
        }
        __syncthreads();
    }

    // ---- epilogue: normalize, write fp16 [B,S,D] ----
    const float il0 = 1.f / (l0 > 0.f ? l0 : 1.f);
    const float il1 = 1.f / (l1 > 0.f ? l1 : 1.f);
    const int qr  = q0 + wid * 16 + (lid >> 2);
    const int col0 = h * DKH + (lid & 3) * 2;
#pragma unroll
    for (int nt = 0; nt < 8; nt++) {
        const int col = col0 + nt * 8;
        {
            __half2 p = __floats2half2_rn(O[nt][0] * il0, O[nt][1] * il0);
            *(__half2*)&O_out[((size_t)bz * SEQ + qr) * BDIM + col] = p;
        }
        {
            __half2 p = __floats2half2_rn(O[nt][2] * il1, O[nt][3] * il1);
            *(__half2*)&O_out[((size_t)bz * SEQ + qr + 8) * BDIM + col] = p;
        }
    }
}

// ======================= weight transpose (fp32 -> fp16 [N,K]) =======================
__global__ __launch_bounds__(256) void wtrans_kernel(
    const float* __restrict__ W, fp16* __restrict__ T16, int K, int N)
{
    __shared__ float t[32][33];
    const int n0 = blockIdx.x * 32, k0 = blockIdx.y * 32;
    const int tx = threadIdx.x, ty = threadIdx.y;
#pragma unroll
    for (int j = 0; j < 4; j++)
        t[ty + j * 8][tx] = W[(size_t)(k0 + ty + j * 8) * N + n0 + tx];
    __syncthreads();
#pragma unroll
    for (int j = 0; j < 4; j++)
        T16[(size_t)(n0 + ty + j * 8) * K + k0 + tx] = __float2half(t[tx][ty + j * 8]);
}

// ======================= fp32 -> fp16 =======================
__global__ __launch_bounds__(256) void cvt_h(
    const float* __restrict__ X, fp16* __restrict__ H)
{
    const int i = (blockIdx.x * 256 + threadIdx.x) * 4;
    const float4 v = *(const float4*)(X + i);
    *(__half2*)(H + i)     = __floats2half2_rn(v.x, v.y);
    *(__half2*)(H + i + 2) = __floats2half2_rn(v.z, v.w);
}

// ======================= LayerNorm (+ optional fp16 output) =======================
__global__ __launch_bounds__(256) void ln_kernel(
    const float* __restrict__ X, const float* __restrict__ g,
    const float* __restrict__ b, float* __restrict__ Y, fp16* __restrict__ Yh)
{
    __shared__ float red[2][8];
    __shared__ float stats[2];
    const int row = blockIdx.x;
    const int tid = threadIdx.x;

    const float4 v = ((const float4*)(X + (size_t)row * BDIM))[tid];
    float s = v.x + v.y + v.z + v.w;
    float q = v.x * v.x + v.y * v.y + v.z * v.z + v.w * v.w;
#pragma unroll
    for (int o = 16; o > 0; o >>= 1) {
        s += __shfl_xor_sync(0xffffffffu, s, o);
        q += __shfl_xor_sync(0xffffffffu, q, o);
    }
    const int lane = tid & 31, w = tid >> 5;
    if (lane == 0) { red[0][w] = s; red[1][w] = q; }
    __syncthreads();
    if (tid < 32) {
        s = (tid < 8) ? red[0][tid] : 0.f;
        q = (tid < 8) ? red[1][tid] : 0.f;
#pragma unroll
        for (int o = 4; o > 0; o >>= 1) {
            s += __shfl_xor_sync(0xffffffffu, s, o);
            q += __shfl_xor_sync(0xffffffffu, q, o);
        }
        if (tid == 0) {
            float mean = s * (1.f / BDIM);
            stats[0] = mean;
            stats[1] = rsqrtf(q * (1.f / BDIM) - mean * mean + 1e-5f);
        }
    }
    __syncthreads();
    const float mean = stats[0], rinv = stats[1];
    const float4 gg = ((const float4*)g)[tid];
    const float4 bb = ((const float4*)b)[tid];
    float4 o4;
    o4.x = (v.x - mean) * rinv * gg.x + bb.x;
    o4.y = (v.y - mean) * rinv * gg.y + bb.y;
    o4.z = (v.z - mean) * rinv * gg.z + bb.z;
    o4.w = (v.w - mean) * rinv * gg.w + bb.w;
    if (Y) ((float4*)(Y + (size_t)row * BDIM))[tid] = o4;
    if (Yh) {
        size_t base = (size_t)row * BDIM + tid * 4;
        *(__half2*)(Yh + base)     = __floats2half2_rn(o4.x, o4.y);
        *(__half2*)(Yh + base + 2) = __floats2half2_rn(o4.z, o4.w);
    }
}

// ======================= launcher =======================
extern "C" void kernel_launch(void* const* d_in, const int* in_sizes, int n_in,
                              void* d_out, int out_size)
{
    const float* x    = (const float*)d_in[0];
    const float* y    = (const float*)d_in[1];
    const int*   mask = (const int*)  d_in[2];
    const float* Wq = (const float*)d_in[3];  const float* bq = (const float*)d_in[4];
    const float* Wk = (const float*)d_in[5];  const float* bk = (const float*)d_in[6];
    const float* Wv = (const float*)d_in[7];  const float* bv = (const float*)d_in[8];
    const float* Wo = (const float*)d_in[9];  const float* bo = (const float*)d_in[10];
    const float* W1 = (const float*)d_in[11]; const float* b1 = (const float*)d_in[12];
    const float* W2 = (const float*)d_in[13]; const float* b2 = (const float*)d_in[14];
    const float* g1 = (const float*)d_in[15]; const float* be1 = (const float*)d_in[16];
    const float* g2 = (const float*)d_in[17]; const float* be2 = (const float*)d_in[18];
    float* out = (float*)d_out;

    float *s1p, *x1p, *s2p;
    fp16 *xh, *yh, *qh, *kh, *vh, *ah, *x1h, *hh;
    fp16 *wq, *wk, *wv, *wo, *w1, *w2;
    cudaGetSymbolAddress((void**)&s1p, g_s1);  cudaGetSymbolAddress((void**)&x1p, g_x1);
    cudaGetSymbolAddress((void**)&s2p, g_s2);
    cudaGetSymbolAddress((void**)&xh, g_xh);   cudaGetSymbolAddress((void**)&yh, g_yh);
    cudaGetSymbolAddress((void**)&qh, g_Qh);   cudaGetSymbolAddress((void**)&kh, g_Kh);
    cudaGetSymbolAddress((void**)&vh, g_Vh);   cudaGetSymbolAddress((void**)&ah, g_ah);
    cudaGetSymbolAddress((void**)&x1h, g_x1h); cudaGetSymbolAddress((void**)&hh, g_hh);
    cudaGetSymbolAddress((void**)&wq, g_wqT);  cudaGetSymbolAddress((void**)&wk, g_wkT);
    cudaGetSymbolAddress((void**)&wv, g_wvT);  cudaGetSymbolAddress((void**)&wo, g_woT);
    cudaGetSymbolAddress((void**)&w1, g_w1T);  cudaGetSymbolAddress((void**)&w2, g_w2T);

    cudaFuncSetAttribute(mma_gemm, cudaFuncAttributeMaxDynamicSharedMemorySize, GEMM_SMEM);
    cudaFuncSetAttribute(attn_tc,  cudaFuncAttributeMaxDynamicSharedMemorySize, AT_SMEM);

    // ---- weight prep (transpose to [N,K] fp16) ----
    dim3 tb(32, 8);
    wtrans_kernel<<<dim3(BDIM / 32, BDIM / 32), tb>>>(Wq, wq, BDIM, BDIM);
    wtrans_kernel<<<dim3(BDIM / 32, BDIM / 32), tb>>>(Wk, wk, BDIM, BDIM);
    wtrans_kernel<<<dim3(BDIM / 32, BDIM / 32), tb>>>(Wv, wv, BDIM, BDIM);
    wtrans_kernel<<<dim3(BDIM / 32, BDIM / 32), tb>>>(Wo, wo, BDIM, BDIM);
    wtrans_kernel<<<dim3(HIDN / 32, BDIM / 32), tb>>>(W1, w1, BDIM, HIDN);
    wtrans_kernel<<<dim3(BDIM / 32, HIDN / 32), tb>>>(W2, w2, HIDN, BDIM);

    // ---- activation fp16 conversion ----
    cvt_h<<<(MROWS * BDIM) / 1024, 256>>>(x, xh);
    cvt_h<<<(MROWS * BDIM) / 1024, 256>>>(y, yh);

    dim3 gD(BDIM / 128, MROWS / 128);
    dim3 gH(HIDN / 128, MROWS / 128);

    // QKV projections -> [B,H,S,DK] fp16
    mma_gemm<<<gD, 256, GEMM_SMEM>>>(xh, wq, bq, nullptr, nullptr, qh, MROWS, BDIM, BDIM, MODE_SPLIT_H);
    mma_gemm<<<gD, 256, GEMM_SMEM>>>(yh, wk, bk, nullptr, nullptr, kh, MROWS, BDIM, BDIM, MODE_SPLIT_H);
    mma_gemm<<<gD, 256, GEMM_SMEM>>>(yh, wv, bv, nullptr, nullptr, vh, MROWS, BDIM, BDIM, MODE_SPLIT_H);

    // tensor-core flash attention -> fp16 [B,S,D]
    attn_tc<<<dim3(SEQ / 128, NH, NB), 256, AT_SMEM>>>(qh, kh, vh, mask, ah);

    // s1 = x + attn @ Wo + bo ; x1 = LN(s1) (+fp16)
    mma_gemm<<<gD, 256, GEMM_SMEM>>>(ah, wo, bo, x, s1p, nullptr, MROWS, BDIM, BDIM, MODE_RES);
    ln_kernel<<<MROWS, 256>>>(s1p, g1, be1, x1p, x1h);

    // FFN
    mma_gemm<<<gH, 256, GEMM_SMEM>>>(x1h, w1, b1, nullptr, nullptr, hh, MROWS, HIDN, BDIM, MODE_RELU_H);
    mma_gemm<<<gD, 256, GEMM_SMEM>>>(hh, w2, b2, x1p, s2p, nullptr, MROWS, BDIM, HIDN, MODE_RES);
    ln_kernel<<<MROWS, 256>>>(s2p, g2, be2, out, nullptr);
}